// round 1
// baseline (speedup 1.0000x reference)
#include <cuda_runtime.h>
#include <cuda_bf16.h>
#include <cstddef>

// Problem dims (fixed by the reference)
#define BB     4
#define SS     2048
#define D_IN   1024
#define D_MODEL 1024
#define NH     16
#define HD     64
#define MROWS  (BB * SS)          // 8192
#define QKV_N  (3 * D_MODEL)      // 3072

// Scratch (allocation-free rule: __device__ globals)
__device__ float g_qkv[(size_t)MROWS * QKV_N];     // 96 MB
__device__ float g_vals[(size_t)MROWS * D_MODEL];  // 32 MB fallback for `values`

// ---------------------------------------------------------------------------
// Generic fp32 GEMM + bias: C[M,N] = A[M,K] @ B[K,N] + bias[N]
// 128x128x16 tile, 256 threads, 8x8 per-thread (split 4+4 quadrants).
// ---------------------------------------------------------------------------
__global__ __launch_bounds__(256) void gemm_bias_kernel(
    const float* __restrict__ A, const float* __restrict__ Bm,
    const float* __restrict__ bias, float* __restrict__ C,
    int M, int N, int K)
{
    const int BM = 128, BN = 128, BK = 16;
    const int APAD = 132;                       // padded stride to tame STS conflicts
    __shared__ float As[BK * APAD];             // As[k][m] (transposed)
    __shared__ float Bs[BK * BN];               // Bs[k][n]

    const int tid = threadIdx.x;
    const int tr = tid >> 4;                    // 0..15 row group
    const int tc = tid & 15;                    // 0..15 col group
    const int m0 = blockIdx.y * BM;
    const int n0 = blockIdx.x * BN;

    float acc[8][8];
#pragma unroll
    for (int i = 0; i < 8; i++)
#pragma unroll
        for (int j = 0; j < 8; j++) acc[i][j] = 0.f;

    for (int kt = 0; kt < K; kt += BK) {
        // A tile: 128 rows x 16 k  (512 float4)
#pragma unroll
        for (int i = 0; i < 2; i++) {
            int l   = tid + i * 256;
            int row = l >> 2;
            int kc4 = (l & 3) * 4;
            float4 v = *(const float4*)&A[(size_t)(m0 + row) * K + kt + kc4];
            As[(kc4 + 0) * APAD + row] = v.x;
            As[(kc4 + 1) * APAD + row] = v.y;
            As[(kc4 + 2) * APAD + row] = v.z;
            As[(kc4 + 3) * APAD + row] = v.w;
        }
        // B tile: 16 k x 128 n  (512 float4)
#pragma unroll
        for (int i = 0; i < 2; i++) {
            int l   = tid + i * 256;
            int kr  = l >> 5;
            int nc4 = (l & 31) * 4;
            *(float4*)&Bs[kr * BN + nc4] =
                *(const float4*)&Bm[(size_t)(kt + kr) * N + n0 + nc4];
        }
        __syncthreads();

#pragma unroll
        for (int kk = 0; kk < BK; kk++) {
            float4 a0 = *(const float4*)&As[kk * APAD + tr * 4];
            float4 a1 = *(const float4*)&As[kk * APAD + 64 + tr * 4];
            float4 b0 = *(const float4*)&Bs[kk * BN + tc * 4];
            float4 b1 = *(const float4*)&Bs[kk * BN + 64 + tc * 4];
            float a[8] = {a0.x, a0.y, a0.z, a0.w, a1.x, a1.y, a1.z, a1.w};
            float b[8] = {b0.x, b0.y, b0.z, b0.w, b1.x, b1.y, b1.z, b1.w};
#pragma unroll
            for (int i = 0; i < 8; i++)
#pragma unroll
                for (int j = 0; j < 8; j++)
                    acc[i][j] = fmaf(a[i], b[j], acc[i][j]);
        }
        __syncthreads();
    }

    // Epilogue: add bias, write the two 4-wide column quadrants per row
#pragma unroll
    for (int i = 0; i < 8; i++) {
        int row = m0 + ((i < 4) ? (tr * 4 + i) : (64 + tr * 4 + (i - 4)));
#pragma unroll
        for (int jq = 0; jq < 2; jq++) {
            int col = n0 + jq * 64 + tc * 4;
            float4 o;
            o.x = acc[i][jq * 4 + 0] + bias[col + 0];
            o.y = acc[i][jq * 4 + 1] + bias[col + 1];
            o.z = acc[i][jq * 4 + 2] + bias[col + 2];
            o.w = acc[i][jq * 4 + 3] + bias[col + 3];
            *(float4*)&C[(size_t)row * N + col] = o;
        }
    }
}

// ---------------------------------------------------------------------------
// Flash attention (fp32), one CTA = 64 q-rows of one (b,h).
// qkv layout: [(b*S+s)][h*192 + {0:q,64:k,128:v} + d]
// Writes values[b,s, h*64+d]  (= the reference's second output, and GEMM2's A)
// ---------------------------------------------------------------------------
#define ATT_PAD 68
#define ATT_SMEM_FLOATS (3 * 64 * ATT_PAD + 64 * 64)
#define ATT_SMEM_BYTES  (ATT_SMEM_FLOATS * 4)

__global__ __launch_bounds__(256) void attn_kernel(
    const float* __restrict__ qkv,
    const float* __restrict__ mask,     // [S,S] additive
    float* __restrict__ vout)           // [B*S, 1024]
{
    extern __shared__ float sm[];
    float* Qs = sm;                       // [64][68]  Qs[d][m]
    float* Ks = Qs + 64 * ATT_PAD;        // [64][68]  Ks[d][n]
    float* Ps = Ks + 64 * ATT_PAD;        // [64][68]  Ps[k][m]
    float* Vs = Ps + 64 * ATT_PAD;        // [64][64]  Vs[k][d]

    const int tid = threadIdx.x;
    const int tr = tid >> 4;              // 0..15: q-row group (4 rows)
    const int tc = tid & 15;              // 0..15: col group (4 cols)
    const int q0 = blockIdx.x * 64;
    const int bh = blockIdx.y;
    const int b  = bh >> 4, h = bh & 15;
    const float scale = 0.125f;           // 1/sqrt(64)

    const float* qbase = qkv + (size_t)b * SS * QKV_N + h * 192;
    const float* kbase = qbase + 64;
    const float* vbase = qbase + 128;

    // Load Q tile transposed: Qs[d][m]
#pragma unroll
    for (int i = 0; i < 4; i++) {
        int l   = tid + i * 256;          // float4 index, 1024 total
        int row = l >> 4;
        int d4  = (l & 15) * 4;
        float4 v = *(const float4*)&qbase[(size_t)(q0 + row) * QKV_N + d4];
        Qs[(d4 + 0) * ATT_PAD + row] = v.x;
        Qs[(d4 + 1) * ATT_PAD + row] = v.y;
        Qs[(d4 + 2) * ATT_PAD + row] = v.z;
        Qs[(d4 + 3) * ATT_PAD + row] = v.w;
    }

    float o[4][4];
    float mrow[4], lrow[4];
#pragma unroll
    for (int i = 0; i < 4; i++) {
        mrow[i] = -1e30f; lrow[i] = 0.f;
#pragma unroll
        for (int j = 0; j < 4; j++) o[i][j] = 0.f;
    }

    for (int kt = 0; kt < SS; kt += 64) {
        __syncthreads();   // prev PV done (and Q visible on first iter)

        // Load K tile (transposed) and V tile (natural)
#pragma unroll
        for (int i = 0; i < 4; i++) {
            int l   = tid + i * 256;
            int row = l >> 4;
            int d4  = (l & 15) * 4;
            float4 kv = *(const float4*)&kbase[(size_t)(kt + row) * QKV_N + d4];
            Ks[(d4 + 0) * ATT_PAD + row] = kv.x;
            Ks[(d4 + 1) * ATT_PAD + row] = kv.y;
            Ks[(d4 + 2) * ATT_PAD + row] = kv.z;
            Ks[(d4 + 3) * ATT_PAD + row] = kv.w;
            float4 vv = *(const float4*)&vbase[(size_t)(kt + row) * QKV_N + d4];
            *(float4*)&Vs[row * 64 + d4] = vv;
        }
        __syncthreads();

        // S = Q K^T
        float s4[4][4];
#pragma unroll
        for (int i = 0; i < 4; i++)
#pragma unroll
            for (int j = 0; j < 4; j++) s4[i][j] = 0.f;

#pragma unroll 16
        for (int kk = 0; kk < 64; kk++) {
            float4 a  = *(const float4*)&Qs[kk * ATT_PAD + tr * 4];
            float4 bb = *(const float4*)&Ks[kk * ATT_PAD + tc * 4];
            float av[4] = {a.x, a.y, a.z, a.w};
            float bv[4] = {bb.x, bb.y, bb.z, bb.w};
#pragma unroll
            for (int i = 0; i < 4; i++)
#pragma unroll
                for (int j = 0; j < 4; j++)
                    s4[i][j] = fmaf(av[i], bv[j], s4[i][j]);
        }

        // scale + additive mask
#pragma unroll
        for (int i = 0; i < 4; i++) {
            float4 mk = *(const float4*)&mask[(size_t)(q0 + tr * 4 + i) * SS + kt + tc * 4];
            s4[i][0] = s4[i][0] * scale + mk.x;
            s4[i][1] = s4[i][1] * scale + mk.y;
            s4[i][2] = s4[i][2] * scale + mk.z;
            s4[i][3] = s4[i][3] * scale + mk.w;
        }

        // Online softmax (row groups of 16 threads; shfl stays in 16-lane half)
#pragma unroll
        for (int i = 0; i < 4; i++) {
            float tm = fmaxf(fmaxf(s4[i][0], s4[i][1]), fmaxf(s4[i][2], s4[i][3]));
#pragma unroll
            for (int off = 8; off >= 1; off >>= 1)
                tm = fmaxf(tm, __shfl_xor_sync(0xffffffffu, tm, off));
            float nm = fmaxf(mrow[i], tm);
            float corr = __expf(mrow[i] - nm);
            mrow[i] = nm;
            float rs = 0.f;
#pragma unroll
            for (int j = 0; j < 4; j++) {
                s4[i][j] = __expf(s4[i][j] - nm);
                rs += s4[i][j];
            }
#pragma unroll
            for (int off = 8; off >= 1; off >>= 1)
                rs += __shfl_xor_sync(0xffffffffu, rs, off);
            lrow[i] = lrow[i] * corr + rs;
#pragma unroll
            for (int j = 0; j < 4; j++) o[i][j] *= corr;
        }

        // Stage P transposed: Ps[k][m]
#pragma unroll
        for (int j = 0; j < 4; j++)
#pragma unroll
            for (int i = 0; i < 4; i++)
                Ps[(tc * 4 + j) * ATT_PAD + tr * 4 + i] = s4[i][j];
        __syncthreads();

        // O += P V
#pragma unroll 16
        for (int kk = 0; kk < 64; kk++) {
            float4 p  = *(const float4*)&Ps[kk * ATT_PAD + tr * 4];
            float4 vv = *(const float4*)&Vs[kk * 64 + tc * 4];
            float pv[4] = {p.x, p.y, p.z, p.w};
            float vvv[4] = {vv.x, vv.y, vv.z, vv.w};
#pragma unroll
            for (int i = 0; i < 4; i++)
#pragma unroll
                for (int j = 0; j < 4; j++)
                    o[i][j] = fmaf(pv[i], vvv[j], o[i][j]);
        }
    }

    // Normalize and write values[b, s, h*64 + d]
#pragma unroll
    for (int i = 0; i < 4; i++) {
        float inv = 1.0f / lrow[i];
        float4 out;
        out.x = o[i][0] * inv;
        out.y = o[i][1] * inv;
        out.z = o[i][2] * inv;
        out.w = o[i][3] * inv;
        size_t row = (size_t)b * SS + q0 + tr * 4 + i;
        *(float4*)&vout[row * D_MODEL + h * HD + tc * 4] = out;
    }
}

// ---------------------------------------------------------------------------
// Launch
// ---------------------------------------------------------------------------
extern "C" void kernel_launch(void* const* d_in, const int* in_sizes, int n_in,
                              void* d_out, int out_size)
{
    const float* x     = (const float*)d_in[0];   // [4,2048,1024]
    const float* mask  = (const float*)d_in[1];   // [1,1,2048,2048]
    const float* W_qkv = (const float*)d_in[2];   // [1024,3072]
    const float* b_qkv = (const float*)d_in[3];   // [3072]
    const float* W_o   = (const float*)d_in[4];   // [1024,1024]
    const float* b_o   = (const float*)d_in[5];   // [1024]
    float* out = (float*)d_out;

    float* qkv_buf = nullptr;
    float* vals_fallback = nullptr;
    cudaGetSymbolAddress((void**)&qkv_buf, g_qkv);
    cudaGetSymbolAddress((void**)&vals_fallback, g_vals);

    // Output is (out, values) flattened: values lives in d_out's second half
    // when the harness sized it for the tuple; otherwise use scratch.
    const size_t half = (size_t)MROWS * D_MODEL;
    float* vbuf = ((size_t)out_size >= 2 * half) ? (out + half) : vals_fallback;

    // 1) qkv = x @ W_qkv + b_qkv
    {
        dim3 grid(QKV_N / 128, MROWS / 128);   // 24 x 64
        gemm_bias_kernel<<<grid, 256>>>(x, W_qkv, b_qkv, qkv_buf,
                                        MROWS, QKV_N, D_IN);
    }

    // 2) attention -> values
    {
        cudaFuncSetAttribute(attn_kernel,
                             cudaFuncAttributeMaxDynamicSharedMemorySize,
                             ATT_SMEM_BYTES);
        dim3 grid(SS / 64, BB * NH);           // 32 x 64
        attn_kernel<<<grid, 256, ATT_SMEM_BYTES>>>(qkv_buf, mask, vbuf);
    }

    // 3) out = values @ W_o + b_o
    {
        dim3 grid(D_MODEL / 128, MROWS / 128); // 8 x 64
        gemm_bias_kernel<<<grid, 256>>>(vbuf, W_o, b_o, out,
                                        MROWS, D_MODEL, D_MODEL);
    }
}

// round 2
// speedup vs baseline: 2.1058x; 2.1058x over previous
#include <cuda_runtime.h>
#include <cuda_bf16.h>
#include <cstddef>

// Problem dims (fixed by the reference)
#define BB      4
#define SS      2048
#define D_IN    1024
#define D_MODEL 1024
#define NH      16
#define HD      64
#define MROWS   (BB * SS)          // 8192
#define QKV_N   (3 * D_MODEL)      // 3072

// Scratch (allocation-free rule: __device__ globals)
__device__ float g_qkv[(size_t)MROWS * QKV_N];     // 96 MB
__device__ float g_vals[(size_t)MROWS * D_MODEL];  // 32 MB fallback for `values`

// ---------------------------------------------------------------------------
// tf32 helpers
// ---------------------------------------------------------------------------
__device__ __forceinline__ unsigned f2tf(float f) {
    unsigned r;
    asm("cvt.rna.tf32.f32 %0, %1;" : "=r"(r) : "f"(f));
    return r;
}

__device__ __forceinline__ void mma1688(float* c, const unsigned* a, const unsigned* b) {
    asm volatile(
        "mma.sync.aligned.m16n8k8.row.col.f32.tf32.tf32.f32 "
        "{%0,%1,%2,%3}, {%4,%5,%6,%7}, {%8,%9}, {%0,%1,%2,%3};"
        : "+f"(c[0]), "+f"(c[1]), "+f"(c[2]), "+f"(c[3])
        : "r"(a[0]), "r"(a[1]), "r"(a[2]), "r"(a[3]), "r"(b[0]), "r"(b[1]));
}

// ---------------------------------------------------------------------------
// TF32 GEMM + bias: C[M,N] = A[M,K] @ B[K,N] + bias[N]
// CTA 128x128x32, 8 warps (2x4), warp tile 64x32 (4 m-tiles x 4 n-tiles of
// m16n8k8). Double-buffered SMEM, register-staged global prefetch.
// SMEM strides: A pad 36 (4 mod 32), B pad 136 (8 mod 32) -> conflict-free
// fragment loads.
// ---------------------------------------------------------------------------
#define GPA 36
#define GPB 136
#define GEMM_SMEM_UINTS (2 * 128 * GPA + 2 * 32 * GPB)   // 9216 + 8704 = 17920
#define GEMM_SMEM_BYTES (GEMM_SMEM_UINTS * 4)            // 71680

__global__ __launch_bounds__(256, 2) void gemm_tf32_kernel(
    const float* __restrict__ A, const float* __restrict__ Bm,
    const float* __restrict__ bias, float* __restrict__ C,
    int M, int N, int K)
{
    extern __shared__ unsigned gsm[];
    unsigned* As[2] = { gsm, gsm + 128 * GPA };
    unsigned* Bs[2] = { gsm + 2 * 128 * GPA, gsm + 2 * 128 * GPA + 32 * GPB };

    const int tid  = threadIdx.x;
    const int wid  = tid >> 5;
    const int lane = tid & 31;
    const int grp  = lane >> 2;
    const int qd   = lane & 3;
    const int wm   = (wid >> 2) * 64;   // warp m offset within CTA
    const int wn   = (wid & 3) * 32;    // warp n offset within CTA
    const int m0   = blockIdx.y * 128;
    const int n0   = blockIdx.x * 128;

    float acc[4][4][4];                 // [im][jn][c0..c3]
#pragma unroll
    for (int im = 0; im < 4; im++)
#pragma unroll
        for (int jn = 0; jn < 4; jn++)
#pragma unroll
            for (int c = 0; c < 4; c++) acc[im][jn][c] = 0.f;

    // prefetch registers
    float4 ra[4], rb[4];

    // --- tile load helpers (lambdas by macro for clarity) ---
#define LOAD_A(kt)                                                           \
    {                                                                        \
        _Pragma("unroll")                                                    \
        for (int i = 0; i < 4; i++) {                                        \
            int f   = tid + i * 256;                                         \
            int row = f >> 3;                                                \
            int kc4 = (f & 7) * 4;                                           \
            ra[i] = *(const float4*)&A[(size_t)(m0 + row) * K + (kt) + kc4]; \
        }                                                                    \
    }
#define LOAD_B(kt)                                                           \
    {                                                                        \
        _Pragma("unroll")                                                    \
        for (int i = 0; i < 4; i++) {                                        \
            int f   = tid + i * 256;                                         \
            int kr  = f >> 5;                                                \
            int nc4 = (f & 31) * 4;                                          \
            rb[i] = *(const float4*)&Bm[(size_t)((kt) + kr) * N + n0 + nc4]; \
        }                                                                    \
    }
#define STORE_AB(buf)                                                        \
    {                                                                        \
        _Pragma("unroll")                                                    \
        for (int i = 0; i < 4; i++) {                                        \
            int f   = tid + i * 256;                                         \
            int row = f >> 3;                                                \
            int kc4 = (f & 7) * 4;                                           \
            unsigned* p = &As[buf][row * GPA + kc4];                         \
            p[0] = f2tf(ra[i].x); p[1] = f2tf(ra[i].y);                      \
            p[2] = f2tf(ra[i].z); p[3] = f2tf(ra[i].w);                      \
        }                                                                    \
        _Pragma("unroll")                                                    \
        for (int i = 0; i < 4; i++) {                                        \
            int f   = tid + i * 256;                                         \
            int kr  = f >> 5;                                                \
            int nc4 = (f & 31) * 4;                                          \
            unsigned* p = &Bs[buf][kr * GPB + nc4];                          \
            p[0] = f2tf(rb[i].x); p[1] = f2tf(rb[i].y);                      \
            p[2] = f2tf(rb[i].z); p[3] = f2tf(rb[i].w);                      \
        }                                                                    \
    }

    const int T = K / 32;
    LOAD_A(0); LOAD_B(0);
    STORE_AB(0);
    __syncthreads();

    for (int t = 0; t < T; t++) {
        int cur = t & 1;
        if (t + 1 < T) { LOAD_A((t + 1) * 32); LOAD_B((t + 1) * 32); }

        const unsigned* as = As[cur];
        const unsigned* bs = Bs[cur];
#pragma unroll
        for (int kk = 0; kk < 4; kk++) {
            unsigned af[4][4];
#pragma unroll
            for (int im = 0; im < 4; im++) {
                int r = wm + im * 16 + grp;
                af[im][0] = as[r * GPA + kk * 8 + qd];
                af[im][1] = as[(r + 8) * GPA + kk * 8 + qd];
                af[im][2] = as[r * GPA + kk * 8 + qd + 4];
                af[im][3] = as[(r + 8) * GPA + kk * 8 + qd + 4];
            }
            unsigned bf[4][2];
#pragma unroll
            for (int jn = 0; jn < 4; jn++) {
                int cl = wn + jn * 8 + grp;
                bf[jn][0] = bs[(kk * 8 + qd) * GPB + cl];
                bf[jn][1] = bs[(kk * 8 + qd + 4) * GPB + cl];
            }
#pragma unroll
            for (int im = 0; im < 4; im++)
#pragma unroll
                for (int jn = 0; jn < 4; jn++)
                    mma1688(acc[im][jn], af[im], bf[jn]);
        }

        if (t + 1 < T) STORE_AB((t + 1) & 1);
        __syncthreads();
    }

    // epilogue: bias + store (float2 per c-pair)
#pragma unroll
    for (int im = 0; im < 4; im++) {
        int rA = m0 + wm + im * 16 + grp;
        int rB = rA + 8;
#pragma unroll
        for (int jn = 0; jn < 4; jn++) {
            int col = n0 + wn + jn * 8 + 2 * qd;
            float bx = bias[col], by = bias[col + 1];
            float2 oA = { acc[im][jn][0] + bx, acc[im][jn][1] + by };
            float2 oB = { acc[im][jn][2] + bx, acc[im][jn][3] + by };
            *(float2*)&C[(size_t)rA * N + col] = oA;
            *(float2*)&C[(size_t)rB * N + col] = oB;
        }
    }
#undef LOAD_A
#undef LOAD_B
#undef STORE_AB
}

// ---------------------------------------------------------------------------
// Flash attention, tf32 mma. One CTA = 64 q-rows of one (b,h); 4 warps, each
// owns 16 q-rows. kv processed in 64-wide tiles.
// qkv layout: [(b*S+s)][h*192 + {0:q,64:k,128:v} + d]
// SMEM pads: Q/K/P 68 (4 mod 32), V 72 (8 mod 32) -> conflict-free frag loads.
// ---------------------------------------------------------------------------
#define AQP 68
#define AVP 72
#define ATT_SMEM_UINTS (3 * 64 * AQP + 64 * AVP)          // 13056 + 4608
#define ATT_SMEM_BYTES (ATT_SMEM_UINTS * 4)               // 70656

__global__ __launch_bounds__(128) void attn_tf32_kernel(
    const float* __restrict__ qkv,
    const float* __restrict__ mask,     // [S,S] additive
    float* __restrict__ vout)           // [B*S, 1024]
{
    extern __shared__ unsigned asm_[];
    unsigned* Qs = asm_;                     // [64][AQP]  Q[m][d]
    unsigned* Ks = Qs + 64 * AQP;            // [64][AQP]  K[n][d]
    unsigned* Ps = Ks + 64 * AQP;            // [64][AQP]  P[m][k]
    unsigned* Vs = Ps + 64 * AQP;            // [64][AVP]  V[k][d]

    const int tid  = threadIdx.x;
    const int wid  = tid >> 5;
    const int lane = tid & 31;
    const int grp  = lane >> 2;
    const int qd   = lane & 3;
    const int q0   = blockIdx.x * 64;
    const int bh   = blockIdx.y;
    const int b    = bh >> 4, h = bh & 15;
    const float scale = 0.125f;              // 1/sqrt(64)

    const int rA = wid * 16 + grp;           // this thread's two rows (local)
    const int rB = rA + 8;

    const float* qbase = qkv + (size_t)b * SS * QKV_N + h * 192;
    const float* kbase = qbase + 64;
    const float* vbase = qbase + 128;

    // load Q tile (64x64), tf32-rounded
#pragma unroll
    for (int i = 0; i < 8; i++) {
        int f   = tid + i * 128;
        int row = f >> 4;
        int c4  = (f & 15) * 4;
        float4 v = *(const float4*)&qbase[(size_t)(q0 + row) * QKV_N + c4];
        unsigned* p = &Qs[row * AQP + c4];
        p[0] = f2tf(v.x); p[1] = f2tf(v.y); p[2] = f2tf(v.z); p[3] = f2tf(v.w);
    }

    float o[8][4];
#pragma unroll
    for (int jn = 0; jn < 8; jn++)
#pragma unroll
        for (int c = 0; c < 4; c++) o[jn][c] = 0.f;
    float mA = -1e30f, mB = -1e30f, lA = 0.f, lB = 0.f;

    const float* mrowA = mask + (size_t)(q0 + rA) * SS;
    const float* mrowB = mask + (size_t)(q0 + rB) * SS;

    for (int kt = 0; kt < SS; kt += 64) {
        __syncthreads();   // prev PV done; Q visible on first iter

        // load K (transposed not needed: [n][d]) and V ([k][d]) tiles
#pragma unroll
        for (int i = 0; i < 8; i++) {
            int f   = tid + i * 128;
            int row = f >> 4;
            int c4  = (f & 15) * 4;
            float4 kv = *(const float4*)&kbase[(size_t)(kt + row) * QKV_N + c4];
            unsigned* pk = &Ks[row * AQP + c4];
            pk[0] = f2tf(kv.x); pk[1] = f2tf(kv.y); pk[2] = f2tf(kv.z); pk[3] = f2tf(kv.w);
            float4 vv = *(const float4*)&vbase[(size_t)(kt + row) * QKV_N + c4];
            unsigned* pv = &Vs[row * AVP + c4];
            pv[0] = f2tf(vv.x); pv[1] = f2tf(vv.y); pv[2] = f2tf(vv.z); pv[3] = f2tf(vv.w);
        }
        __syncthreads();

        // S = Q K^T : m16 x n64 x k64 per warp
        float s[8][4];
#pragma unroll
        for (int jn = 0; jn < 8; jn++)
#pragma unroll
            for (int c = 0; c < 4; c++) s[jn][c] = 0.f;

#pragma unroll
        for (int kk = 0; kk < 8; kk++) {
            unsigned a[4];
            a[0] = Qs[rA * AQP + kk * 8 + qd];
            a[1] = Qs[rB * AQP + kk * 8 + qd];
            a[2] = Qs[rA * AQP + kk * 8 + qd + 4];
            a[3] = Qs[rB * AQP + kk * 8 + qd + 4];
#pragma unroll
            for (int jn = 0; jn < 8; jn++) {
                unsigned bf[2];
                bf[0] = Ks[(jn * 8 + grp) * AQP + kk * 8 + qd];
                bf[1] = Ks[(jn * 8 + grp) * AQP + kk * 8 + qd + 4];
                mma1688(s[jn], a, bf);
            }
        }

        // scale + mask
#pragma unroll
        for (int jn = 0; jn < 8; jn++) {
            int col = kt + jn * 8 + 2 * qd;
            float2 mk0 = *(const float2*)&mrowA[col];
            float2 mk1 = *(const float2*)&mrowB[col];
            s[jn][0] = fmaf(s[jn][0], scale, mk0.x);
            s[jn][1] = fmaf(s[jn][1], scale, mk0.y);
            s[jn][2] = fmaf(s[jn][2], scale, mk1.x);
            s[jn][3] = fmaf(s[jn][3], scale, mk1.y);
        }

        // online softmax (row stats live in 4-lane quads)
        float pA = -1e30f, pB = -1e30f;
#pragma unroll
        for (int jn = 0; jn < 8; jn++) {
            pA = fmaxf(pA, fmaxf(s[jn][0], s[jn][1]));
            pB = fmaxf(pB, fmaxf(s[jn][2], s[jn][3]));
        }
        pA = fmaxf(pA, __shfl_xor_sync(0xffffffffu, pA, 1));
        pA = fmaxf(pA, __shfl_xor_sync(0xffffffffu, pA, 2));
        pB = fmaxf(pB, __shfl_xor_sync(0xffffffffu, pB, 1));
        pB = fmaxf(pB, __shfl_xor_sync(0xffffffffu, pB, 2));

        float nA = fmaxf(mA, pA), nB = fmaxf(mB, pB);
        float cA = __expf(mA - nA), cB = __expf(mB - nB);
        mA = nA; mB = nB;

        float sA = 0.f, sB = 0.f;
#pragma unroll
        for (int jn = 0; jn < 8; jn++) {
            s[jn][0] = __expf(s[jn][0] - nA);
            s[jn][1] = __expf(s[jn][1] - nA);
            s[jn][2] = __expf(s[jn][2] - nB);
            s[jn][3] = __expf(s[jn][3] - nB);
            sA += s[jn][0] + s[jn][1];
            sB += s[jn][2] + s[jn][3];
        }
        sA += __shfl_xor_sync(0xffffffffu, sA, 1);
        sA += __shfl_xor_sync(0xffffffffu, sA, 2);
        sB += __shfl_xor_sync(0xffffffffu, sB, 1);
        sB += __shfl_xor_sync(0xffffffffu, sB, 2);
        lA = lA * cA + sA;
        lB = lB * cB + sB;
#pragma unroll
        for (int jn = 0; jn < 8; jn++) {
            o[jn][0] *= cA; o[jn][1] *= cA;
            o[jn][2] *= cB; o[jn][3] *= cB;
        }

        // stage P (tf32) — each warp touches only its own 16 rows
#pragma unroll
        for (int jn = 0; jn < 8; jn++) {
            uint2 wA = { f2tf(s[jn][0]), f2tf(s[jn][1]) };
            uint2 wB = { f2tf(s[jn][2]), f2tf(s[jn][3]) };
            *(uint2*)&Ps[rA * AQP + jn * 8 + 2 * qd] = wA;
            *(uint2*)&Ps[rB * AQP + jn * 8 + 2 * qd] = wB;
        }
        __syncwarp();

        // O += P V : m16 x n64 x k64 per warp
#pragma unroll
        for (int kk = 0; kk < 8; kk++) {
            unsigned a[4];
            a[0] = Ps[rA * AQP + kk * 8 + qd];
            a[1] = Ps[rB * AQP + kk * 8 + qd];
            a[2] = Ps[rA * AQP + kk * 8 + qd + 4];
            a[3] = Ps[rB * AQP + kk * 8 + qd + 4];
#pragma unroll
            for (int jn = 0; jn < 8; jn++) {
                unsigned bf[2];
                bf[0] = Vs[(kk * 8 + qd) * AVP + jn * 8 + grp];
                bf[1] = Vs[(kk * 8 + qd + 4) * AVP + jn * 8 + grp];
                mma1688(o[jn], a, bf);
            }
        }
    }

    // normalize + write values[b, s, h*64 + d]
    float iA = 1.f / lA, iB = 1.f / lB;
    size_t gRA = (size_t)b * SS + q0 + rA;
    size_t gRB = (size_t)b * SS + q0 + rB;
#pragma unroll
    for (int jn = 0; jn < 8; jn++) {
        int col = h * HD + jn * 8 + 2 * qd;
        float2 oA = { o[jn][0] * iA, o[jn][1] * iA };
        float2 oB = { o[jn][2] * iB, o[jn][3] * iB };
        *(float2*)&vout[gRA * D_MODEL + col] = oA;
        *(float2*)&vout[gRB * D_MODEL + col] = oB;
    }
}

// ---------------------------------------------------------------------------
// Launch
// ---------------------------------------------------------------------------
extern "C" void kernel_launch(void* const* d_in, const int* in_sizes, int n_in,
                              void* d_out, int out_size)
{
    const float* x     = (const float*)d_in[0];   // [4,2048,1024]
    const float* mask  = (const float*)d_in[1];   // [1,1,2048,2048]
    const float* W_qkv = (const float*)d_in[2];   // [1024,3072]
    const float* b_qkv = (const float*)d_in[3];   // [3072]
    const float* W_o   = (const float*)d_in[4];   // [1024,1024]
    const float* b_o   = (const float*)d_in[5];   // [1024]
    float* out = (float*)d_out;

    float* qkv_buf = nullptr;
    float* vals_fallback = nullptr;
    cudaGetSymbolAddress((void**)&qkv_buf, g_qkv);
    cudaGetSymbolAddress((void**)&vals_fallback, g_vals);

    const size_t half = (size_t)MROWS * D_MODEL;
    float* vbuf = ((size_t)out_size >= 2 * half) ? (out + half) : vals_fallback;

    static bool attr_done = false;
    if (!attr_done) {
        cudaFuncSetAttribute(gemm_tf32_kernel,
                             cudaFuncAttributeMaxDynamicSharedMemorySize,
                             GEMM_SMEM_BYTES);
        cudaFuncSetAttribute(attn_tf32_kernel,
                             cudaFuncAttributeMaxDynamicSharedMemorySize,
                             ATT_SMEM_BYTES);
        attr_done = true;
    }

    // 1) qkv = x @ W_qkv + b_qkv
    {
        dim3 grid(QKV_N / 128, MROWS / 128);   // 24 x 64
        gemm_tf32_kernel<<<grid, 256, GEMM_SMEM_BYTES>>>(
            x, W_qkv, b_qkv, qkv_buf, MROWS, QKV_N, D_IN);
    }

    // 2) attention -> values
    {
        dim3 grid(SS / 64, BB * NH);           // 32 x 64
        attn_tf32_kernel<<<grid, 128, ATT_SMEM_BYTES>>>(qkv_buf, mask, vbuf);
    }

    // 3) out = values @ W_o + b_o
    {
        dim3 grid(D_MODEL / 128, MROWS / 128); // 8 x 64
        gemm_tf32_kernel<<<grid, 256, GEMM_SMEM_BYTES>>>(
            vbuf, W_o, b_o, out, MROWS, D_MODEL, D_MODEL);
    }
}

// round 3
// speedup vs baseline: 2.1744x; 1.0326x over previous
#include <cuda_runtime.h>
#include <cuda_bf16.h>
#include <cstddef>

#define BB      4
#define SS      2048
#define D_IN    1024
#define D_MODEL 1024
#define NH      16
#define HD      64
#define MROWS   (BB * SS)          // 8192
#define QKV_N   (3 * D_MODEL)      // 3072

// Scratch (__device__ globals; no allocation allowed)
__device__ float g_x[(size_t)MROWS * D_IN];        // 32 MB rounded x
__device__ float g_wqkv[(size_t)D_IN * QKV_N];     // 12 MB rounded W_qkv
__device__ float g_wo[(size_t)D_MODEL * D_MODEL];  //  4 MB rounded W_o
__device__ float g_qkv[(size_t)MROWS * QKV_N];     // 96 MB rounded qkv
__device__ float g_vr[(size_t)MROWS * D_MODEL];    // 32 MB rounded values
__device__ float g_vals[(size_t)MROWS * D_MODEL];  // 32 MB fallback for values
__device__ int   g_mnz;                            // mask-nonzero flag

// ---------------------------------------------------------------------------
// helpers
// ---------------------------------------------------------------------------
__device__ __forceinline__ unsigned f2tf(float f) {
    unsigned r;
    asm("cvt.rna.tf32.f32 %0, %1;" : "=r"(r) : "f"(f));
    return r;
}

__device__ __forceinline__ void mma1688(float* c, const unsigned* a, const unsigned* b) {
    asm volatile(
        "mma.sync.aligned.m16n8k8.row.col.f32.tf32.tf32.f32 "
        "{%0,%1,%2,%3}, {%4,%5,%6,%7}, {%8,%9}, {%0,%1,%2,%3};"
        : "+f"(c[0]), "+f"(c[1]), "+f"(c[2]), "+f"(c[3])
        : "r"(a[0]), "r"(a[1]), "r"(a[2]), "r"(a[3]), "r"(b[0]), "r"(b[1]));
}

__device__ __forceinline__ void cpa16(unsigned dst, const void* src) {
    asm volatile("cp.async.cg.shared.global [%0], [%1], 16;\n" :: "r"(dst), "l"(src));
}
#define CP_COMMIT() asm volatile("cp.async.commit_group;\n")
#define CP_WAIT1()  asm volatile("cp.async.wait_group 1;\n")
#define CP_WAIT0()  asm volatile("cp.async.wait_group 0;\n")

// ---------------------------------------------------------------------------
// pre-pass kernels
// ---------------------------------------------------------------------------
__global__ void round_tf32_kernel(const float4* __restrict__ in,
                                  float4* __restrict__ out, int n4) {
    int i = blockIdx.x * blockDim.x + threadIdx.x;
    int st = gridDim.x * blockDim.x;
    for (; i < n4; i += st) {
        float4 v = in[i];
        v.x = __uint_as_float(f2tf(v.x));
        v.y = __uint_as_float(f2tf(v.y));
        v.z = __uint_as_float(f2tf(v.z));
        v.w = __uint_as_float(f2tf(v.w));
        out[i] = v;
    }
}

__global__ void reset_flag_kernel(int* f) { *f = 0; }

__global__ void mask_scan_kernel(const float4* __restrict__ m, int n4, int* flag) {
    int i = blockIdx.x * blockDim.x + threadIdx.x;
    int st = gridDim.x * blockDim.x;
    int any = 0;
    for (; i < n4; i += st) {
        float4 v = m[i];
        any |= (v.x != 0.f) | (v.y != 0.f) | (v.z != 0.f) | (v.w != 0.f);
    }
    any = __syncthreads_or(any);
    if (threadIdx.x == 0 && any) atomicOr(flag, 1);
}

// ---------------------------------------------------------------------------
// TF32 GEMM + bias: C = A@B + bias. Inputs pre-rounded to tf32 bit patterns.
// CTA 128x128x32, 8 warps (2x4), warp 64x32. 3-stage cp.async pipeline,
// XOR-swizzled smem, conflict-free fragment loads, no STS, no cvt.
// roundOut: write tf32-rounded output (for qkv).
// ---------------------------------------------------------------------------
#define GEMM_STAGE_BYTES 32768                      // 16KB A + 16KB B
#define GEMM_SMEM_BYTES  (3 * GEMM_STAGE_BYTES)     // 96 KB

__global__ __launch_bounds__(256, 2) void gemm_tf32_pipe(
    const float* __restrict__ A, const float* __restrict__ Bm,
    const float* __restrict__ bias, float* __restrict__ C,
    int M, int N, int K, int roundOut)
{
    extern __shared__ float gsm[];
    unsigned sbase = (unsigned)__cvta_generic_to_shared(gsm);

    const int tid  = threadIdx.x;
    const int wid  = tid >> 5;
    const int lane = tid & 31;
    const int grp  = lane >> 2;
    const int qd   = lane & 3;
    const int wm   = (wid >> 2) * 64;
    const int wn   = (wid & 3) * 32;
    const int m0   = blockIdx.y * 128;
    const int n0   = blockIdx.x * 128;

    float acc[4][4][4];
#pragma unroll
    for (int im = 0; im < 4; im++)
#pragma unroll
        for (int jn = 0; jn < 4; jn++)
#pragma unroll
            for (int c = 0; c < 4; c++) acc[im][jn][c] = 0.f;

#define G_ISSUE(t, stg) do {                                                  \
    unsigned sa = sbase + (stg) * GEMM_STAGE_BYTES;                           \
    unsigned sb = sa + 16384;                                                 \
    const float* gA = A + (size_t)m0 * K + (size_t)(t) * 32;                  \
    const float* gB = Bm + (size_t)(t) * 32 * N + n0;                         \
    _Pragma("unroll")                                                         \
    for (int i = 0; i < 4; i++) {                                             \
        int g = tid + i * 256; int row = g >> 3; int kg = g & 7;              \
        cpa16(sa + (unsigned)(row * 32 + ((kg ^ (row & 7)) << 2)) * 4,        \
              gA + (size_t)row * K + kg * 4);                                 \
    }                                                                         \
    _Pragma("unroll")                                                         \
    for (int i = 0; i < 4; i++) {                                             \
        int g = tid + i * 256; int row = g >> 5; int ng = g & 31;             \
        cpa16(sb + (unsigned)(row * 128 + ((ng ^ ((row & 3) << 1)) << 2)) * 4,\
              gB + (size_t)row * N + ng * 4);                                 \
    }                                                                         \
    CP_COMMIT();                                                              \
} while (0)

    const int T = K >> 5;
    G_ISSUE(0, 0);
    G_ISSUE(1, 1);
    CP_WAIT1();
    __syncthreads();

    int stg = 0, nstg = 2;
    for (int t = 0; t < T; t++) {
        if (t + 2 < T) G_ISSUE(t + 2, nstg);

        const unsigned* ua = (const unsigned*)gsm + stg * 8192;
        const unsigned* ub = ua + 4096;
#pragma unroll
        for (int kk = 0; kk < 4; kk++) {
            unsigned af[4][4];
#pragma unroll
            for (int im = 0; im < 4; im++) {
                int r  = wm + im * 16 + grp;
                int s0 = ((kk * 2) ^ grp) << 2;
                int s1 = ((kk * 2 + 1) ^ grp) << 2;
                af[im][0] = ua[r * 32 + s0 + qd];
                af[im][1] = ua[(r + 8) * 32 + s0 + qd];
                af[im][2] = ua[r * 32 + s1 + qd];
                af[im][3] = ua[(r + 8) * 32 + s1 + qd];
            }
            unsigned bf[4][2];
            int sw = qd << 1;
#pragma unroll
            for (int jn = 0; jn < 4; jn++) {
                int cl = wn + jn * 8 + grp;
                int col = (((cl >> 2) ^ sw) << 2) + (cl & 3);
                bf[jn][0] = ub[(kk * 8 + qd) * 128 + col];
                bf[jn][1] = ub[(kk * 8 + qd + 4) * 128 + col];
            }
#pragma unroll
            for (int im = 0; im < 4; im++)
#pragma unroll
                for (int jn = 0; jn < 4; jn++)
                    mma1688(acc[im][jn], af[im], bf[jn]);
        }

        if (t + 2 < T) CP_WAIT1(); else CP_WAIT0();
        __syncthreads();
        stg  = (stg  + 1 == 3) ? 0 : stg  + 1;
        nstg = (nstg + 1 == 3) ? 0 : nstg + 1;
    }
#undef G_ISSUE

    // epilogue
#pragma unroll
    for (int im = 0; im < 4; im++) {
        int rA = m0 + wm + im * 16 + grp;
        int rB = rA + 8;
#pragma unroll
        for (int jn = 0; jn < 4; jn++) {
            int col = n0 + wn + jn * 8 + 2 * qd;
            float bx = bias[col], by = bias[col + 1];
            float2 oA = { acc[im][jn][0] + bx, acc[im][jn][1] + by };
            float2 oB = { acc[im][jn][2] + bx, acc[im][jn][3] + by };
            if (roundOut) {
                oA.x = __uint_as_float(f2tf(oA.x));
                oA.y = __uint_as_float(f2tf(oA.y));
                oB.x = __uint_as_float(f2tf(oB.x));
                oB.y = __uint_as_float(f2tf(oB.y));
            }
            *(float2*)&C[(size_t)rA * N + col] = oA;
            *(float2*)&C[(size_t)rB * N + col] = oB;
        }
    }
}

// ---------------------------------------------------------------------------
// Flash attention, tf32 mma, cp.async double-buffered K/V, Q in registers.
// One CTA = 64 q-rows of one (b,h); 4 warps x 16 rows. qkv pre-rounded.
// Writes vout (fp32 exact) and vr (tf32-rounded copy for GEMM2).
// SMEM: K[2][64x64] | V[2][64x64] | P[64x64]   = 80 KB, XOR swizzled.
// ---------------------------------------------------------------------------
#define ATT_SMEM_BYTES 81920

__global__ __launch_bounds__(128) void attn_pipe(
    const float* __restrict__ qkv,
    const float* __restrict__ mask,
    const int* __restrict__ mnz,
    float* __restrict__ vout,
    float* __restrict__ vr)
{
    extern __shared__ float sm[];
    unsigned sbase = (unsigned)__cvta_generic_to_shared(sm);
    const unsigned* usm = (const unsigned*)sm;
    unsigned* upw = (unsigned*)sm + 16384;          // P region (words)

    const int tid  = threadIdx.x;
    const int wid  = tid >> 5;
    const int lane = tid & 31;
    const int grp  = lane >> 2;
    const int qd   = lane & 3;
    const int q0   = blockIdx.x * 64;
    const int bh   = blockIdx.y;
    const int b    = bh >> 4, h = bh & 15;
    const float scale = 0.125f;

    const int rA = wid * 16 + grp;
    const int rB = rA + 8;

    const float* qbase = qkv + (size_t)b * SS * QKV_N + h * 192;
    const float* kbase = qbase + 64;
    const float* vbase = qbase + 128;
    const int use_mask = *mnz;

    // Q fragments held in registers for the whole kernel
    unsigned qa[8][4];
    {
        const unsigned* qAp = (const unsigned*)qbase + (size_t)(q0 + rA) * QKV_N;
        const unsigned* qBp = (const unsigned*)qbase + (size_t)(q0 + rB) * QKV_N;
#pragma unroll
        for (int kk = 0; kk < 8; kk++) {
            qa[kk][0] = qAp[kk * 8 + qd];
            qa[kk][1] = qBp[kk * 8 + qd];
            qa[kk][2] = qAp[kk * 8 + qd + 4];
            qa[kk][3] = qBp[kk * 8 + qd + 4];
        }
    }

    float o[8][4];
#pragma unroll
    for (int jn = 0; jn < 8; jn++)
#pragma unroll
        for (int c = 0; c < 4; c++) o[jn][c] = 0.f;
    float mA = -1e30f, mB = -1e30f, lA = 0.f, lB = 0.f;

    const float* mrowA = mask + (size_t)(q0 + rA) * SS;
    const float* mrowB = mask + (size_t)(q0 + rB) * SS;

#define A_ISSUE(t) do {                                                       \
    int st = (t) & 1;                                                         \
    unsigned ks = sbase + (unsigned)st * 16384;                               \
    unsigned vs = sbase + 32768 + (unsigned)st * 16384;                       \
    const float* gK = kbase + (size_t)(t) * 64 * QKV_N;                       \
    const float* gV = vbase + (size_t)(t) * 64 * QKV_N;                       \
    _Pragma("unroll")                                                         \
    for (int i = 0; i < 8; i++) {                                             \
        int g = tid + i * 128; int row = g >> 4; int kg = g & 15;             \
        cpa16(ks + (unsigned)(row * 64 + ((kg ^ (row & 7)) << 2)) * 4,        \
              gK + (size_t)row * QKV_N + kg * 4);                             \
        cpa16(vs + (unsigned)(row * 64 + ((kg ^ ((row & 3) << 1)) << 2)) * 4, \
              gV + (size_t)row * QKV_N + kg * 4);                             \
    }                                                                         \
    CP_COMMIT();                                                              \
} while (0)

    A_ISSUE(0);

    for (int t = 0; t < SS / 64; t++) {
        if (t + 1 < SS / 64) { A_ISSUE(t + 1); CP_WAIT1(); }
        else CP_WAIT0();
        __syncthreads();

        const unsigned* uk = usm + (t & 1) * 4096;
        const unsigned* uv = usm + 8192 + (t & 1) * 4096;

        // S = Q K^T
        float s[8][4];
#pragma unroll
        for (int jn = 0; jn < 8; jn++)
#pragma unroll
            for (int c = 0; c < 4; c++) s[jn][c] = 0.f;

#pragma unroll
        for (int kk = 0; kk < 8; kk++) {
            int s0 = ((kk * 2) ^ grp) << 2;
            int s1 = ((kk * 2 + 1) ^ grp) << 2;
#pragma unroll
            for (int jn = 0; jn < 8; jn++) {
                int cl = jn * 8 + grp;
                unsigned bf[2];
                bf[0] = uk[cl * 64 + s0 + qd];
                bf[1] = uk[cl * 64 + s1 + qd];
                mma1688(s[jn], qa[kk], bf);
            }
        }

        // scale (+ mask only if nonzero)
        if (use_mask) {
#pragma unroll
            for (int jn = 0; jn < 8; jn++) {
                int col = t * 64 + jn * 8 + 2 * qd;
                float2 mk0 = *(const float2*)&mrowA[col];
                float2 mk1 = *(const float2*)&mrowB[col];
                s[jn][0] = fmaf(s[jn][0], scale, mk0.x);
                s[jn][1] = fmaf(s[jn][1], scale, mk0.y);
                s[jn][2] = fmaf(s[jn][2], scale, mk1.x);
                s[jn][3] = fmaf(s[jn][3], scale, mk1.y);
            }
        } else {
#pragma unroll
            for (int jn = 0; jn < 8; jn++)
#pragma unroll
                for (int c = 0; c < 4; c++) s[jn][c] *= scale;
        }

        // online softmax (quad-local stats)
        float pA = -1e30f, pB = -1e30f;
#pragma unroll
        for (int jn = 0; jn < 8; jn++) {
            pA = fmaxf(pA, fmaxf(s[jn][0], s[jn][1]));
            pB = fmaxf(pB, fmaxf(s[jn][2], s[jn][3]));
        }
        pA = fmaxf(pA, __shfl_xor_sync(0xffffffffu, pA, 1));
        pA = fmaxf(pA, __shfl_xor_sync(0xffffffffu, pA, 2));
        pB = fmaxf(pB, __shfl_xor_sync(0xffffffffu, pB, 1));
        pB = fmaxf(pB, __shfl_xor_sync(0xffffffffu, pB, 2));

        float nA = fmaxf(mA, pA), nB = fmaxf(mB, pB);
        float cA = __expf(mA - nA), cB = __expf(mB - nB);
        mA = nA; mB = nB;

        float sA = 0.f, sB = 0.f;
#pragma unroll
        for (int jn = 0; jn < 8; jn++) {
            s[jn][0] = __expf(s[jn][0] - nA);
            s[jn][1] = __expf(s[jn][1] - nA);
            s[jn][2] = __expf(s[jn][2] - nB);
            s[jn][3] = __expf(s[jn][3] - nB);
            sA += s[jn][0] + s[jn][1];
            sB += s[jn][2] + s[jn][3];
        }
        sA += __shfl_xor_sync(0xffffffffu, sA, 1);
        sA += __shfl_xor_sync(0xffffffffu, sA, 2);
        sB += __shfl_xor_sync(0xffffffffu, sB, 1);
        sB += __shfl_xor_sync(0xffffffffu, sB, 2);
        lA = lA * cA + sA;
        lB = lB * cB + sB;
#pragma unroll
        for (int jn = 0; jn < 8; jn++) {
            o[jn][0] *= cA; o[jn][1] *= cA;
            o[jn][2] *= cB; o[jn][3] *= cB;
        }

        // stage P (tf32), swizzled, per-warp rows only
#pragma unroll
        for (int jn = 0; jn < 8; jn++) {
            int kg   = jn * 2 + (qd >> 1);
            int colw = ((kg ^ grp) << 2) + 2 * (qd & 1);
            uint2 wA = { f2tf(s[jn][0]), f2tf(s[jn][1]) };
            uint2 wB = { f2tf(s[jn][2]), f2tf(s[jn][3]) };
            *(uint2*)(upw + rA * 64 + colw) = wA;
            *(uint2*)(upw + rB * 64 + colw) = wB;
        }
        __syncwarp();

        // O += P V
#pragma unroll
        for (int kk = 0; kk < 8; kk++) {
            int s0 = ((kk * 2) ^ grp) << 2;
            int s1 = ((kk * 2 + 1) ^ grp) << 2;
            unsigned pa[4];
            pa[0] = upw[rA * 64 + s0 + qd];
            pa[1] = upw[rB * 64 + s0 + qd];
            pa[2] = upw[rA * 64 + s1 + qd];
            pa[3] = upw[rB * 64 + s1 + qd];
            int rowv0 = (kk * 8 + qd) * 64;
            int rowv1 = (kk * 8 + qd + 4) * 64;
            int sw = qd << 1;
#pragma unroll
            for (int jn = 0; jn < 8; jn++) {
                int d  = jn * 8 + grp;
                int col = (((d >> 2) ^ sw) << 2) + (d & 3);
                unsigned bf[2];
                bf[0] = uv[rowv0 + col];
                bf[1] = uv[rowv1 + col];
                mma1688(o[jn], pa, bf);
            }
        }
        __syncthreads();
    }
#undef A_ISSUE

    // normalize + write values (fp32) and rounded copy
    float iA = 1.f / lA, iB = 1.f / lB;
    size_t gRA = (size_t)b * SS + q0 + rA;
    size_t gRB = (size_t)b * SS + q0 + rB;
#pragma unroll
    for (int jn = 0; jn < 8; jn++) {
        int col = h * HD + jn * 8 + 2 * qd;
        float2 oA = { o[jn][0] * iA, o[jn][1] * iA };
        float2 oB = { o[jn][2] * iB, o[jn][3] * iB };
        *(float2*)&vout[gRA * D_MODEL + col] = oA;
        *(float2*)&vout[gRB * D_MODEL + col] = oB;
        float2 rAv = { __uint_as_float(f2tf(oA.x)), __uint_as_float(f2tf(oA.y)) };
        float2 rBv = { __uint_as_float(f2tf(oB.x)), __uint_as_float(f2tf(oB.y)) };
        *(float2*)&vr[gRA * D_MODEL + col] = rAv;
        *(float2*)&vr[gRB * D_MODEL + col] = rBv;
    }
}

// ---------------------------------------------------------------------------
// Launch
// ---------------------------------------------------------------------------
extern "C" void kernel_launch(void* const* d_in, const int* in_sizes, int n_in,
                              void* d_out, int out_size)
{
    const float* x     = (const float*)d_in[0];
    const float* mask  = (const float*)d_in[1];
    const float* W_qkv = (const float*)d_in[2];
    const float* b_qkv = (const float*)d_in[3];
    const float* W_o   = (const float*)d_in[4];
    const float* b_o   = (const float*)d_in[5];
    float* out = (float*)d_out;

    float *gx, *gwqkv, *gwo, *qkv_buf, *gvr, *vals_fb;
    int* flag;
    cudaGetSymbolAddress((void**)&gx, g_x);
    cudaGetSymbolAddress((void**)&gwqkv, g_wqkv);
    cudaGetSymbolAddress((void**)&gwo, g_wo);
    cudaGetSymbolAddress((void**)&qkv_buf, g_qkv);
    cudaGetSymbolAddress((void**)&gvr, g_vr);
    cudaGetSymbolAddress((void**)&vals_fb, g_vals);
    cudaGetSymbolAddress((void**)&flag, g_mnz);

    const size_t half = (size_t)MROWS * D_MODEL;
    float* vbuf = ((size_t)out_size >= 2 * half) ? (out + half) : vals_fb;

    static bool attr_done = false;
    if (!attr_done) {
        cudaFuncSetAttribute(gemm_tf32_pipe,
                             cudaFuncAttributeMaxDynamicSharedMemorySize,
                             GEMM_SMEM_BYTES);
        cudaFuncSetAttribute(attn_pipe,
                             cudaFuncAttributeMaxDynamicSharedMemorySize,
                             ATT_SMEM_BYTES);
        attr_done = true;
    }

    // mask flag + pre-rounded inputs
    reset_flag_kernel<<<1, 1>>>(flag);
    mask_scan_kernel<<<1024, 256>>>((const float4*)mask, SS * SS / 4, flag);
    round_tf32_kernel<<<2048, 256>>>((const float4*)x, (float4*)gx,
                                     MROWS * D_IN / 4);
    round_tf32_kernel<<<1024, 256>>>((const float4*)W_qkv, (float4*)gwqkv,
                                     D_IN * QKV_N / 4);
    round_tf32_kernel<<<512, 256>>>((const float4*)W_o, (float4*)gwo,
                                    D_MODEL * D_MODEL / 4);

    // 1) qkv = x @ W_qkv + b_qkv  (rounded output)
    {
        dim3 grid(QKV_N / 128, MROWS / 128);
        gemm_tf32_pipe<<<grid, 256, GEMM_SMEM_BYTES>>>(
            gx, gwqkv, b_qkv, qkv_buf, MROWS, QKV_N, D_IN, 1);
    }

    // 2) attention -> values (fp32) + rounded copy
    {
        dim3 grid(SS / 64, BB * NH);
        attn_pipe<<<grid, 128, ATT_SMEM_BYTES>>>(qkv_buf, mask, flag, vbuf, gvr);
    }

    // 3) out = values @ W_o + b_o
    {
        dim3 grid(D_MODEL / 128, MROWS / 128);
        gemm_tf32_pipe<<<grid, 256, GEMM_SMEM_BYTES>>>(
            gvr, gwo, b_o, out, MROWS, D_MODEL, D_MODEL, 0);
    }
}

// round 4
// speedup vs baseline: 3.3654x; 1.5477x over previous
#include <cuda_runtime.h>
#include <cuda_bf16.h>
#include <cstddef>

#define BB      4
#define SS      2048
#define D_IN    1024
#define D_MODEL 1024
#define NH      16
#define HD      64
#define MROWS   (BB * SS)          // 8192
#define QKV_N   (3 * D_MODEL)      // 3072

// Scratch (__device__ globals; no allocation allowed)
__device__ float g_x[(size_t)MROWS * D_IN];        // 32 MB rounded x
__device__ float g_wqkv[(size_t)D_IN * QKV_N];     // 12 MB rounded W_qkv
__device__ float g_wo[(size_t)D_MODEL * D_MODEL];  //  4 MB rounded W_o
__device__ float g_qkv[(size_t)MROWS * QKV_N];     // 96 MB rounded qkv
__device__ float g_vr[(size_t)MROWS * D_MODEL];    // 32 MB rounded values
__device__ float g_vals[(size_t)MROWS * D_MODEL];  // 32 MB fallback for values
__device__ int   g_mnz;                            // mask-nonzero flag

// ---------------------------------------------------------------------------
// helpers
// ---------------------------------------------------------------------------
__device__ __forceinline__ unsigned f2tf(float f) {
    unsigned r;
    asm("cvt.rna.tf32.f32 %0, %1;" : "=r"(r) : "f"(f));
    return r;
}

__device__ __forceinline__ void mma1688(float* c, const unsigned* a, const unsigned* b) {
    asm volatile(
        "mma.sync.aligned.m16n8k8.row.col.f32.tf32.tf32.f32 "
        "{%0,%1,%2,%3}, {%4,%5,%6,%7}, {%8,%9}, {%0,%1,%2,%3};"
        : "+f"(c[0]), "+f"(c[1]), "+f"(c[2]), "+f"(c[3])
        : "r"(a[0]), "r"(a[1]), "r"(a[2]), "r"(a[3]), "r"(b[0]), "r"(b[1]));
}

__device__ __forceinline__ void cpa16(unsigned dst, const void* src) {
    asm volatile("cp.async.cg.shared.global [%0], [%1], 16;\n" :: "r"(dst), "l"(src));
}
#define CP_COMMIT() asm volatile("cp.async.commit_group;\n")
#define CP_WAIT1()  asm volatile("cp.async.wait_group 1;\n")
#define CP_WAIT0()  asm volatile("cp.async.wait_group 0;\n")

// ---------------------------------------------------------------------------
// pre-pass kernels
// ---------------------------------------------------------------------------
__global__ void round_tf32_kernel(const float4* __restrict__ in,
                                  float4* __restrict__ out, int n4) {
    int i = blockIdx.x * blockDim.x + threadIdx.x;
    int st = gridDim.x * blockDim.x;
    for (; i < n4; i += st) {
        float4 v = in[i];
        v.x = __uint_as_float(f2tf(v.x));
        v.y = __uint_as_float(f2tf(v.y));
        v.z = __uint_as_float(f2tf(v.z));
        v.w = __uint_as_float(f2tf(v.w));
        out[i] = v;
    }
}

__global__ void reset_flag_kernel(int* f) { *f = 0; }

__global__ void mask_scan_kernel(const float4* __restrict__ m, int n4, int* flag) {
    int i = blockIdx.x * blockDim.x + threadIdx.x;
    int st = gridDim.x * blockDim.x;
    int any = 0;
    for (; i < n4; i += st) {
        float4 v = m[i];
        any |= (v.x != 0.f) | (v.y != 0.f) | (v.z != 0.f) | (v.w != 0.f);
    }
    any = __syncthreads_or(any);
    if (threadIdx.x == 0 && any) atomicOr(flag, 1);
}

// ---------------------------------------------------------------------------
// TF32 GEMM + bias: C = A@B + bias. Inputs pre-rounded to tf32 bit patterns.
// CTA 128x128x32, 8 warps (2x4), warp 64x32. 3-stage cp.async pipeline,
// XOR-swizzled smem, conflict-free fragment loads, no STS, no cvt.
// roundOut: write tf32-rounded output (for qkv).
// ---------------------------------------------------------------------------
#define GEMM_STAGE_BYTES 32768                      // 16KB A + 16KB B
#define GEMM_SMEM_BYTES  (3 * GEMM_STAGE_BYTES)     // 96 KB

__global__ __launch_bounds__(256, 2) void gemm_tf32_pipe(
    const float* __restrict__ A, const float* __restrict__ Bm,
    const float* __restrict__ bias, float* __restrict__ C,
    int M, int N, int K, int roundOut)
{
    extern __shared__ float gsm[];
    unsigned sbase = (unsigned)__cvta_generic_to_shared(gsm);

    const int tid  = threadIdx.x;
    const int wid  = tid >> 5;
    const int lane = tid & 31;
    const int grp  = lane >> 2;
    const int qd   = lane & 3;
    const int wm   = (wid >> 2) * 64;
    const int wn   = (wid & 3) * 32;
    const int m0   = blockIdx.y * 128;
    const int n0   = blockIdx.x * 128;

    float acc[4][4][4];
#pragma unroll
    for (int im = 0; im < 4; im++)
#pragma unroll
        for (int jn = 0; jn < 4; jn++)
#pragma unroll
            for (int c = 0; c < 4; c++) acc[im][jn][c] = 0.f;

#define G_ISSUE(t, stg) do {                                                  \
    unsigned sa = sbase + (stg) * GEMM_STAGE_BYTES;                           \
    unsigned sb = sa + 16384;                                                 \
    const float* gA = A + (size_t)m0 * K + (size_t)(t) * 32;                  \
    const float* gB = Bm + (size_t)(t) * 32 * N + n0;                         \
    _Pragma("unroll")                                                         \
    for (int i = 0; i < 4; i++) {                                             \
        int g = tid + i * 256; int row = g >> 3; int kg = g & 7;              \
        cpa16(sa + (unsigned)(row * 32 + ((kg ^ (row & 7)) << 2)) * 4,        \
              gA + (size_t)row * K + kg * 4);                                 \
    }                                                                         \
    _Pragma("unroll")                                                         \
    for (int i = 0; i < 4; i++) {                                             \
        int g = tid + i * 256; int row = g >> 5; int ng = g & 31;             \
        cpa16(sb + (unsigned)(row * 128 + ((ng ^ ((row & 3) << 1)) << 2)) * 4,\
              gB + (size_t)row * N + ng * 4);                                 \
    }                                                                         \
    CP_COMMIT();                                                              \
} while (0)

    const int T = K >> 5;
    G_ISSUE(0, 0);
    G_ISSUE(1, 1);
    CP_WAIT1();
    __syncthreads();

    int stg = 0, nstg = 2;
    for (int t = 0; t < T; t++) {
        if (t + 2 < T) G_ISSUE(t + 2, nstg);

        const unsigned* ua = (const unsigned*)gsm + stg * 8192;
        const unsigned* ub = ua + 4096;
#pragma unroll
        for (int kk = 0; kk < 4; kk++) {
            unsigned af[4][4];
#pragma unroll
            for (int im = 0; im < 4; im++) {
                int r  = wm + im * 16 + grp;
                int s0 = ((kk * 2) ^ grp) << 2;
                int s1 = ((kk * 2 + 1) ^ grp) << 2;
                af[im][0] = ua[r * 32 + s0 + qd];
                af[im][1] = ua[(r + 8) * 32 + s0 + qd];
                af[im][2] = ua[r * 32 + s1 + qd];
                af[im][3] = ua[(r + 8) * 32 + s1 + qd];
            }
            unsigned bf[4][2];
            int sw = qd << 1;
#pragma unroll
            for (int jn = 0; jn < 4; jn++) {
                int cl = wn + jn * 8 + grp;
                int col = (((cl >> 2) ^ sw) << 2) + (cl & 3);
                bf[jn][0] = ub[(kk * 8 + qd) * 128 + col];
                bf[jn][1] = ub[(kk * 8 + qd + 4) * 128 + col];
            }
#pragma unroll
            for (int im = 0; im < 4; im++)
#pragma unroll
                for (int jn = 0; jn < 4; jn++)
                    mma1688(acc[im][jn], af[im], bf[jn]);
        }

        if (t + 2 < T) CP_WAIT1(); else CP_WAIT0();
        __syncthreads();
        stg  = (stg  + 1 == 3) ? 0 : stg  + 1;
        nstg = (nstg + 1 == 3) ? 0 : nstg + 1;
    }
#undef G_ISSUE

    // epilogue
#pragma unroll
    for (int im = 0; im < 4; im++) {
        int rA = m0 + wm + im * 16 + grp;
        int rB = rA + 8;
#pragma unroll
        for (int jn = 0; jn < 4; jn++) {
            int col = n0 + wn + jn * 8 + 2 * qd;
            float bx = bias[col], by = bias[col + 1];
            float2 oA = { acc[im][jn][0] + bx, acc[im][jn][1] + by };
            float2 oB = { acc[im][jn][2] + bx, acc[im][jn][3] + by };
            if (roundOut) {
                oA.x = __uint_as_float(f2tf(oA.x));
                oA.y = __uint_as_float(f2tf(oA.y));
                oB.x = __uint_as_float(f2tf(oB.x));
                oB.y = __uint_as_float(f2tf(oB.y));
            }
            *(float2*)&C[(size_t)rA * N + col] = oA;
            *(float2*)&C[(size_t)rB * N + col] = oB;
        }
    }
}

// ---------------------------------------------------------------------------
// Flash attention, tf32 mma, cp.async double-buffered K/V, Q in registers.
// One CTA = 64 q-rows of one (b,h); 4 warps x 16 rows. qkv pre-rounded.
// Writes vout (fp32 exact) and vr (tf32-rounded copy for GEMM2).
// SMEM: K[2][64x64] | V[2][64x64] | P[64x64]   = 80 KB, XOR swizzled.
// ---------------------------------------------------------------------------
#define ATT_SMEM_BYTES 81920

__global__ __launch_bounds__(128) void attn_pipe(
    const float* __restrict__ qkv,
    const float* __restrict__ mask,
    const int* __restrict__ mnz,
    float* __restrict__ vout,
    float* __restrict__ vr)
{
    extern __shared__ float sm[];
    unsigned sbase = (unsigned)__cvta_generic_to_shared(sm);
    const unsigned* usm = (const unsigned*)sm;
    unsigned* upw = (unsigned*)sm + 16384;          // P region (words)

    const int tid  = threadIdx.x;
    const int wid  = tid >> 5;
    const int lane = tid & 31;
    const int grp  = lane >> 2;
    const int qd   = lane & 3;
    const int q0   = blockIdx.x * 64;
    const int bh   = blockIdx.y;
    const int b    = bh >> 4, h = bh & 15;
    const float scale = 0.125f;

    const int rA = wid * 16 + grp;
    const int rB = rA + 8;

    const float* qbase = qkv + (size_t)b * SS * QKV_N + h * 192;
    const float* kbase = qbase + 64;
    const float* vbase = qbase + 128;
    const int use_mask = *mnz;

    // Q fragments held in registers for the whole kernel
    unsigned qa[8][4];
    {
        const unsigned* qAp = (const unsigned*)qbase + (size_t)(q0 + rA) * QKV_N;
        const unsigned* qBp = (const unsigned*)qbase + (size_t)(q0 + rB) * QKV_N;
#pragma unroll
        for (int kk = 0; kk < 8; kk++) {
            qa[kk][0] = qAp[kk * 8 + qd];
            qa[kk][1] = qBp[kk * 8 + qd];
            qa[kk][2] = qAp[kk * 8 + qd + 4];
            qa[kk][3] = qBp[kk * 8 + qd + 4];
        }
    }

    float o[8][4];
#pragma unroll
    for (int jn = 0; jn < 8; jn++)
#pragma unroll
        for (int c = 0; c < 4; c++) o[jn][c] = 0.f;
    float mA = -1e30f, mB = -1e30f, lA = 0.f, lB = 0.f;

    const float* mrowA = mask + (size_t)(q0 + rA) * SS;
    const float* mrowB = mask + (size_t)(q0 + rB) * SS;

#define A_ISSUE(t) do {                                                       \
    int st = (t) & 1;                                                         \
    unsigned ks = sbase + (unsigned)st * 16384;                               \
    unsigned vs = sbase + 32768 + (unsigned)st * 16384;                       \
    const float* gK = kbase + (size_t)(t) * 64 * QKV_N;                       \
    const float* gV = vbase + (size_t)(t) * 64 * QKV_N;                       \
    _Pragma("unroll")                                                         \
    for (int i = 0; i < 8; i++) {                                             \
        int g = tid + i * 128; int row = g >> 4; int kg = g & 15;             \
        cpa16(ks + (unsigned)(row * 64 + ((kg ^ (row & 7)) << 2)) * 4,        \
              gK + (size_t)row * QKV_N + kg * 4);                             \
        cpa16(vs + (unsigned)(row * 64 + ((kg ^ ((row & 3) << 1)) << 2)) * 4, \
              gV + (size_t)row * QKV_N + kg * 4);                             \
    }                                                                         \
    CP_COMMIT();                                                              \
} while (0)

    A_ISSUE(0);

    for (int t = 0; t < SS / 64; t++) {
        if (t + 1 < SS / 64) { A_ISSUE(t + 1); CP_WAIT1(); }
        else CP_WAIT0();
        __syncthreads();

        const unsigned* uk = usm + (t & 1) * 4096;
        const unsigned* uv = usm + 8192 + (t & 1) * 4096;

        // S = Q K^T
        float s[8][4];
#pragma unroll
        for (int jn = 0; jn < 8; jn++)
#pragma unroll
            for (int c = 0; c < 4; c++) s[jn][c] = 0.f;

#pragma unroll
        for (int kk = 0; kk < 8; kk++) {
            int s0 = ((kk * 2) ^ grp) << 2;
            int s1 = ((kk * 2 + 1) ^ grp) << 2;
#pragma unroll
            for (int jn = 0; jn < 8; jn++) {
                int cl = jn * 8 + grp;
                unsigned bf[2];
                bf[0] = uk[cl * 64 + s0 + qd];
                bf[1] = uk[cl * 64 + s1 + qd];
                mma1688(s[jn], qa[kk], bf);
            }
        }

        // scale (+ mask only if nonzero)
        if (use_mask) {
#pragma unroll
            for (int jn = 0; jn < 8; jn++) {
                int col = t * 64 + jn * 8 + 2 * qd;
                float2 mk0 = *(const float2*)&mrowA[col];
                float2 mk1 = *(const float2*)&mrowB[col];
                s[jn][0] = fmaf(s[jn][0], scale, mk0.x);
                s[jn][1] = fmaf(s[jn][1], scale, mk0.y);
                s[jn][2] = fmaf(s[jn][2], scale, mk1.x);
                s[jn][3] = fmaf(s[jn][3], scale, mk1.y);
            }
        } else {
#pragma unroll
            for (int jn = 0; jn < 8; jn++)
#pragma unroll
                for (int c = 0; c < 4; c++) s[jn][c] *= scale;
        }

        // online softmax (quad-local stats)
        float pA = -1e30f, pB = -1e30f;
#pragma unroll
        for (int jn = 0; jn < 8; jn++) {
            pA = fmaxf(pA, fmaxf(s[jn][0], s[jn][1]));
            pB = fmaxf(pB, fmaxf(s[jn][2], s[jn][3]));
        }
        pA = fmaxf(pA, __shfl_xor_sync(0xffffffffu, pA, 1));
        pA = fmaxf(pA, __shfl_xor_sync(0xffffffffu, pA, 2));
        pB = fmaxf(pB, __shfl_xor_sync(0xffffffffu, pB, 1));
        pB = fmaxf(pB, __shfl_xor_sync(0xffffffffu, pB, 2));

        float nA = fmaxf(mA, pA), nB = fmaxf(mB, pB);
        float cA = __expf(mA - nA), cB = __expf(mB - nB);
        mA = nA; mB = nB;

        float sA = 0.f, sB = 0.f;
#pragma unroll
        for (int jn = 0; jn < 8; jn++) {
            s[jn][0] = __expf(s[jn][0] - nA);
            s[jn][1] = __expf(s[jn][1] - nA);
            s[jn][2] = __expf(s[jn][2] - nB);
            s[jn][3] = __expf(s[jn][3] - nB);
            sA += s[jn][0] + s[jn][1];
            sB += s[jn][2] + s[jn][3];
        }
        sA += __shfl_xor_sync(0xffffffffu, sA, 1);
        sA += __shfl_xor_sync(0xffffffffu, sA, 2);
        sB += __shfl_xor_sync(0xffffffffu, sB, 1);
        sB += __shfl_xor_sync(0xffffffffu, sB, 2);
        lA = lA * cA + sA;
        lB = lB * cB + sB;
#pragma unroll
        for (int jn = 0; jn < 8; jn++) {
            o[jn][0] *= cA; o[jn][1] *= cA;
            o[jn][2] *= cB; o[jn][3] *= cB;
        }

        // stage P (tf32), swizzled, per-warp rows only
#pragma unroll
        for (int jn = 0; jn < 8; jn++) {
            int kg   = jn * 2 + (qd >> 1);
            int colw = ((kg ^ grp) << 2) + 2 * (qd & 1);
            uint2 wA = { f2tf(s[jn][0]), f2tf(s[jn][1]) };
            uint2 wB = { f2tf(s[jn][2]), f2tf(s[jn][3]) };
            *(uint2*)(upw + rA * 64 + colw) = wA;
            *(uint2*)(upw + rB * 64 + colw) = wB;
        }
        __syncwarp();

        // O += P V
#pragma unroll
        for (int kk = 0; kk < 8; kk++) {
            int s0 = ((kk * 2) ^ grp) << 2;
            int s1 = ((kk * 2 + 1) ^ grp) << 2;
            unsigned pa[4];
            pa[0] = upw[rA * 64 + s0 + qd];
            pa[1] = upw[rB * 64 + s0 + qd];
            pa[2] = upw[rA * 64 + s1 + qd];
            pa[3] = upw[rB * 64 + s1 + qd];
            int rowv0 = (kk * 8 + qd) * 64;
            int rowv1 = (kk * 8 + qd + 4) * 64;
            int sw = qd << 1;
#pragma unroll
            for (int jn = 0; jn < 8; jn++) {
                int d  = jn * 8 + grp;
                int col = (((d >> 2) ^ sw) << 2) + (d & 3);
                unsigned bf[2];
                bf[0] = uv[rowv0 + col];
                bf[1] = uv[rowv1 + col];
                mma1688(o[jn], pa, bf);
            }
        }
        __syncthreads();
    }
#undef A_ISSUE

    // normalize + write values (fp32) and rounded copy
    float iA = 1.f / lA, iB = 1.f / lB;
    size_t gRA = (size_t)b * SS + q0 + rA;
    size_t gRB = (size_t)b * SS + q0 + rB;
#pragma unroll
    for (int jn = 0; jn < 8; jn++) {
        int col = h * HD + jn * 8 + 2 * qd;
        float2 oA = { o[jn][0] * iA, o[jn][1] * iA };
        float2 oB = { o[jn][2] * iB, o[jn][3] * iB };
        *(float2*)&vout[gRA * D_MODEL + col] = oA;
        *(float2*)&vout[gRB * D_MODEL + col] = oB;
        float2 rAv = { __uint_as_float(f2tf(oA.x)), __uint_as_float(f2tf(oA.y)) };
        float2 rBv = { __uint_as_float(f2tf(oB.x)), __uint_as_float(f2tf(oB.y)) };
        *(float2*)&vr[gRA * D_MODEL + col] = rAv;
        *(float2*)&vr[gRB * D_MODEL + col] = rBv;
    }
}

// ---------------------------------------------------------------------------
// Launch
// ---------------------------------------------------------------------------
extern "C" void kernel_launch(void* const* d_in, const int* in_sizes, int n_in,
                              void* d_out, int out_size)
{
    const float* x     = (const float*)d_in[0];
    const float* mask  = (const float*)d_in[1];
    const float* W_qkv = (const float*)d_in[2];
    const float* b_qkv = (const float*)d_in[3];
    const float* W_o   = (const float*)d_in[4];
    const float* b_o   = (const float*)d_in[5];
    float* out = (float*)d_out;

    float *gx, *gwqkv, *gwo, *qkv_buf, *gvr, *vals_fb;
    int* flag;
    cudaGetSymbolAddress((void**)&gx, g_x);
    cudaGetSymbolAddress((void**)&gwqkv, g_wqkv);
    cudaGetSymbolAddress((void**)&gwo, g_wo);
    cudaGetSymbolAddress((void**)&qkv_buf, g_qkv);
    cudaGetSymbolAddress((void**)&gvr, g_vr);
    cudaGetSymbolAddress((void**)&vals_fb, g_vals);
    cudaGetSymbolAddress((void**)&flag, g_mnz);

    const size_t half = (size_t)MROWS * D_MODEL;
    float* vbuf = ((size_t)out_size >= 2 * half) ? (out + half) : vals_fb;

    static bool attr_done = false;
    if (!attr_done) {
        cudaFuncSetAttribute(gemm_tf32_pipe,
                             cudaFuncAttributeMaxDynamicSharedMemorySize,
                             GEMM_SMEM_BYTES);
        cudaFuncSetAttribute(attn_pipe,
                             cudaFuncAttributeMaxDynamicSharedMemorySize,
                             ATT_SMEM_BYTES);
        attr_done = true;
    }

    // mask flag + pre-rounded inputs
    reset_flag_kernel<<<1, 1>>>(flag);
    mask_scan_kernel<<<1024, 256>>>((const float4*)mask, SS * SS / 4, flag);
    round_tf32_kernel<<<2048, 256>>>((const float4*)x, (float4*)gx,
                                     MROWS * D_IN / 4);
    round_tf32_kernel<<<1024, 256>>>((const float4*)W_qkv, (float4*)gwqkv,
                                     D_IN * QKV_N / 4);
    round_tf32_kernel<<<512, 256>>>((const float4*)W_o, (float4*)gwo,
                                    D_MODEL * D_MODEL / 4);

    // 1) qkv = x @ W_qkv + b_qkv  (rounded output)
    {
        dim3 grid(QKV_N / 128, MROWS / 128);
        gemm_tf32_pipe<<<grid, 256, GEMM_SMEM_BYTES>>>(
            gx, gwqkv, b_qkv, qkv_buf, MROWS, QKV_N, D_IN, 1);
    }

    // 2) attention -> values (fp32) + rounded copy
    {
        dim3 grid(SS / 64, BB * NH);
        attn_pipe<<<grid, 128, ATT_SMEM_BYTES>>>(qkv_buf, mask, flag, vbuf, gvr);
    }

    // 3) out = values @ W_o + b_o
    {
        dim3 grid(D_MODEL / 128, MROWS / 128);
        gemm_tf32_pipe<<<grid, 256, GEMM_SMEM_BYTES>>>(
            gvr, gwo, b_o, out, MROWS, D_MODEL, D_MODEL, 0);
    }
}

// round 6
// speedup vs baseline: 3.5904x; 1.0669x over previous
#include <cuda_runtime.h>
#include <cuda_bf16.h>
#include <cstddef>

#define BB      4
#define SS      2048
#define D_IN    1024
#define D_MODEL 1024
#define NH      16
#define HD      64
#define MROWS   (BB * SS)          // 8192
#define QKV_N   (3 * D_MODEL)      // 3072

// Scratch (__device__ globals; no allocation allowed)
__device__ float g_x[(size_t)MROWS * D_IN];        // rounded + k-interleaved x
__device__ float g_wqkv[(size_t)D_IN * QKV_N];     // rounded W_qkv
__device__ float g_wo[(size_t)D_MODEL * D_MODEL];  // rounded W_o
__device__ float g_qkv[(size_t)MROWS * QKV_N];     // rounded qkv (natural layout)
__device__ float g_vr[(size_t)MROWS * D_MODEL];    // rounded + k-interleaved values
__device__ float g_vals[(size_t)MROWS * D_MODEL];  // fallback for values
__device__ int   g_mnz;                            // mask-nonzero flag

// ---------------------------------------------------------------------------
// helpers
// ---------------------------------------------------------------------------
__device__ __forceinline__ unsigned f2tf(float f) {
    unsigned r;
    asm("cvt.rna.tf32.f32 %0, %1;" : "=r"(r) : "f"(f));
    return r;
}

__device__ __forceinline__ void mma1688(float* c, const unsigned* a, const unsigned* b) {
    asm volatile(
        "mma.sync.aligned.m16n8k8.row.col.f32.tf32.tf32.f32 "
        "{%0,%1,%2,%3}, {%4,%5,%6,%7}, {%8,%9}, {%0,%1,%2,%3};"
        : "+f"(c[0]), "+f"(c[1]), "+f"(c[2]), "+f"(c[3])
        : "r"(a[0]), "r"(a[1]), "r"(a[2]), "r"(a[3]), "r"(b[0]), "r"(b[1]));
}

__device__ __forceinline__ void cpa16(unsigned dst, const void* src) {
    asm volatile("cp.async.cg.shared.global [%0], [%1], 16;\n" :: "r"(dst), "l"(src));
}
#define CP_COMMIT() asm volatile("cp.async.commit_group;\n")
#define CP_WAIT1()  asm volatile("cp.async.wait_group 1;\n")
#define CP_WAIT0()  asm volatile("cp.async.wait_group 0;\n")

// in-8-group k permute: k -> ((k&3)<<1) | ((k>>2)&1)
__device__ __forceinline__ int perm8(int k) {
    return ((k & 3) << 1) | ((k >> 2) & 1);
}

// ---------------------------------------------------------------------------
// pre-pass kernels
// ---------------------------------------------------------------------------
__global__ void round_tf32_kernel(const float4* __restrict__ in,
                                  float4* __restrict__ out, int n4) {
    int i = blockIdx.x * blockDim.x + threadIdx.x;
    int st = gridDim.x * blockDim.x;
    for (; i < n4; i += st) {
        float4 v = in[i];
        v.x = __uint_as_float(f2tf(v.x));
        v.y = __uint_as_float(f2tf(v.y));
        v.z = __uint_as_float(f2tf(v.z));
        v.w = __uint_as_float(f2tf(v.w));
        out[i] = v;
    }
}

// round + k-interleave within each 8-float group along last dim
__global__ void round_perm_kernel(const float4* __restrict__ in,
                                  float* __restrict__ out, int n4) {
    int i = blockIdx.x * blockDim.x + threadIdx.x;
    int st = gridDim.x * blockDim.x;
    for (; i < n4; i += st) {
        float4 v = in[i];
        int kbase = i * 4;              // logical flat index of v.x
        int gbase = kbase & ~7;         // 8-group start (rows are multiples of 8)
        float vals[4] = { v.x, v.y, v.z, v.w };
#pragma unroll
        for (int j = 0; j < 4; j++) {
            int k = kbase + j;
            out[gbase + perm8(k & 7)] = __uint_as_float(f2tf(vals[j]));
        }
    }
}

__global__ void reset_flag_kernel(int* f) { *f = 0; }

__global__ void mask_scan_kernel(const float4* __restrict__ m, int n4, int* flag) {
    int i = blockIdx.x * blockDim.x + threadIdx.x;
    int st = gridDim.x * blockDim.x;
    int any = 0;
    for (; i < n4; i += st) {
        float4 v = m[i];
        any |= (v.x != 0.f) | (v.y != 0.f) | (v.z != 0.f) | (v.w != 0.f);
    }
    any = __syncthreads_or(any);
    if (threadIdx.x == 0 && any) atomicOr(flag, 1);
}

// ---------------------------------------------------------------------------
// TF32 GEMM + bias: C = A@B + bias.
// A is pre-rounded AND k-interleaved (perm8 within 8-groups). B pre-rounded.
// CTA 128x128x32, 8 warps, warp 64x32, 3-stage cp.async.
// A-frag loads are LDS.64 (conflict-free via hash swizzle), B-frags LDS.32.
// roundOut=1: tf32-round the output (qkv, natural N layout).
// ---------------------------------------------------------------------------
#define GEMM_STAGE_BYTES 32768                      // 16KB A + 16KB B
#define GEMM_SMEM_BYTES  (3 * GEMM_STAGE_BYTES)     // 96 KB

__global__ __launch_bounds__(256, 2) void gemm_tf32_pipe(
    const float* __restrict__ A, const float* __restrict__ Bm,
    const float* __restrict__ bias, float* __restrict__ C,
    int M, int N, int K, int roundOut)
{
    extern __shared__ float gsm[];
    unsigned sbase = (unsigned)__cvta_generic_to_shared(gsm);

    const int tid  = threadIdx.x;
    const int wid  = tid >> 5;
    const int lane = tid & 31;
    const int grp  = lane >> 2;
    const int qd   = lane & 3;
    const int wm   = (wid >> 2) * 64;
    const int wn   = (wid & 3) * 32;
    const int m0   = blockIdx.y * 128;
    const int n0   = blockIdx.x * 128;
    const int hg   = ((grp & 3) << 1) | ((grp >> 2) & 1);   // row hash for frags

    float acc[4][4][4];
#pragma unroll
    for (int im = 0; im < 4; im++)
#pragma unroll
        for (int jn = 0; jn < 4; jn++)
#pragma unroll
            for (int c = 0; c < 4; c++) acc[im][jn][c] = 0.f;

#define G_ISSUE(t, stg) do {                                                   \
    unsigned sa = sbase + (stg) * GEMM_STAGE_BYTES;                            \
    unsigned sb = sa + 16384;                                                  \
    const float* gA = A + (size_t)m0 * K + (size_t)(t) * 32;                   \
    const float* gB = Bm + (size_t)(t) * 32 * N + n0;                          \
    _Pragma("unroll")                                                          \
    for (int i = 0; i < 4; i++) {                                              \
        int g = tid + i * 256; int row = g >> 3; int kg = g & 7;               \
        int hr = ((row & 3) << 1) | ((row >> 2) & 1);                          \
        cpa16(sa + (unsigned)(row * 32 + ((kg ^ hr) << 2)) * 4,                \
              gA + (size_t)row * K + kg * 4);                                  \
    }                                                                          \
    _Pragma("unroll")                                                          \
    for (int i = 0; i < 4; i++) {                                              \
        int g = tid + i * 256; int row = g >> 5; int ng = g & 31;              \
        cpa16(sb + (unsigned)(row * 128 + ((ng ^ ((row & 3) << 1)) << 2)) * 4, \
              gB + (size_t)row * N + ng * 4);                                  \
    }                                                                          \
    CP_COMMIT();                                                               \
} while (0)

    const int T = K >> 5;
    G_ISSUE(0, 0);
    G_ISSUE(1, 1);
    CP_WAIT1();
    __syncthreads();

    int stg = 0, nstg = 2;
    for (int t = 0; t < T; t++) {
        if (t + 2 < T) G_ISSUE(t + 2, nstg);

        const unsigned* ua = (const unsigned*)gsm + stg * 8192;
        const unsigned* ub = ua + 4096;
#pragma unroll
        for (int kk = 0; kk < 4; kk++) {
            int cb = 2 * kk + (qd >> 1);
            int wo = 2 * (qd & 1);
            unsigned af[4][4];
#pragma unroll
            for (int im = 0; im < 4; im++) {
                int r = wm + im * 16 + grp;
                // logical k pair (8kk+qd, 8kk+qd+4) is physically adjacent;
                // hash hr is invariant under row+8 (bits {0,1} and {2 of >>2}
                // unchanged), so BOTH rows use cb ^ hg.  (round-5 bug: ^1)
                uint2 x = *(const uint2*)(ua + r * 32 + ((cb ^ hg) << 2) + wo);
                uint2 y = *(const uint2*)(ua + (r + 8) * 32 + ((cb ^ hg) << 2) + wo);
                af[im][0] = x.x; af[im][1] = y.x;
                af[im][2] = x.y; af[im][3] = y.y;
            }
            unsigned bf[4][2];
            int sw = qd << 1;
#pragma unroll
            for (int jn = 0; jn < 4; jn++) {
                int cl = wn + jn * 8 + grp;
                int col = (((cl >> 2) ^ sw) << 2) + (cl & 3);
                bf[jn][0] = ub[(kk * 8 + qd) * 128 + col];
                bf[jn][1] = ub[(kk * 8 + qd + 4) * 128 + col];
            }
#pragma unroll
            for (int im = 0; im < 4; im++)
#pragma unroll
                for (int jn = 0; jn < 4; jn++)
                    mma1688(acc[im][jn], af[im], bf[jn]);
        }

        if (t + 2 < T) CP_WAIT1(); else CP_WAIT0();
        __syncthreads();
        stg  = (stg  + 1 == 3) ? 0 : stg  + 1;
        nstg = (nstg + 1 == 3) ? 0 : nstg + 1;
    }
#undef G_ISSUE

    // epilogue (natural N layout)
#pragma unroll
    for (int im = 0; im < 4; im++) {
        int rA = m0 + wm + im * 16 + grp;
        int rB = rA + 8;
#pragma unroll
        for (int jn = 0; jn < 4; jn++) {
            int col = n0 + wn + jn * 8 + 2 * qd;
            float bx = bias[col], by = bias[col + 1];
            float2 oA = { acc[im][jn][0] + bx, acc[im][jn][1] + by };
            float2 oB = { acc[im][jn][2] + bx, acc[im][jn][3] + by };
            if (roundOut) {
                oA.x = __uint_as_float(f2tf(oA.x));
                oA.y = __uint_as_float(f2tf(oA.y));
                oB.x = __uint_as_float(f2tf(oB.x));
                oB.y = __uint_as_float(f2tf(oB.y));
            }
            *(float2*)&C[(size_t)rA * N + col] = oA;
            *(float2*)&C[(size_t)rB * N + col] = oB;
        }
    }
}

// ---------------------------------------------------------------------------
// Flash attention, tf32 mma. 256 threads, 8 warps x 16 q-rows = 128 q-rows/CTA
// sharing a double-buffered 64-wide K/V tile. Q fragments in registers.
// Writes vout (fp32, natural) and vr (tf32-rounded, k-interleaved for GEMM2).
// SMEM: K[2][64x64] | V[2][64x64] | P[128x64]  = 96 KB, XOR swizzled.
// ---------------------------------------------------------------------------
#define ATT_SMEM_BYTES 98304

__global__ __launch_bounds__(256, 2) void attn_pipe(
    const float* __restrict__ qkv,
    const float* __restrict__ mask,
    const int* __restrict__ mnz,
    float* __restrict__ vout,
    float* __restrict__ vr)
{
    extern __shared__ float sm[];
    unsigned sbase = (unsigned)__cvta_generic_to_shared(sm);
    const unsigned* usm = (const unsigned*)sm;
    unsigned* upw = (unsigned*)sm + 16384;          // P region (128x64 words)

    const int tid  = threadIdx.x;
    const int wid  = tid >> 5;
    const int lane = tid & 31;
    const int grp  = lane >> 2;
    const int qd   = lane & 3;
    const int q0   = blockIdx.x * 128;
    const int bh   = blockIdx.y;
    const int b    = bh >> 4, h = bh & 15;
    const float scale = 0.125f;

    const int rA = wid * 16 + grp;      // local q-row (0..127)
    const int rB = rA + 8;

    const float* qbase = qkv + (size_t)b * SS * QKV_N + h * 192;
    const float* kbase = qbase + 64;
    const float* vbase = qbase + 128;
    const int use_mask = *mnz;

    // Q fragments in registers for the whole kernel
    unsigned qa[8][4];
    {
        const unsigned* qAp = (const unsigned*)qbase + (size_t)(q0 + rA) * QKV_N;
        const unsigned* qBp = (const unsigned*)qbase + (size_t)(q0 + rB) * QKV_N;
#pragma unroll
        for (int kk = 0; kk < 8; kk++) {
            qa[kk][0] = qAp[kk * 8 + qd];
            qa[kk][1] = qBp[kk * 8 + qd];
            qa[kk][2] = qAp[kk * 8 + qd + 4];
            qa[kk][3] = qBp[kk * 8 + qd + 4];
        }
    }

    float o[8][4];
#pragma unroll
    for (int jn = 0; jn < 8; jn++)
#pragma unroll
        for (int c = 0; c < 4; c++) o[jn][c] = 0.f;
    float mA = -1e30f, mB = -1e30f, lA = 0.f, lB = 0.f;

    const float* mrowA = mask + (size_t)(q0 + rA) * SS;
    const float* mrowB = mask + (size_t)(q0 + rB) * SS;

#define A_ISSUE(t) do {                                                       \
    int st = (t) & 1;                                                         \
    unsigned ks = sbase + (unsigned)st * 16384;                               \
    unsigned vs = sbase + 32768 + (unsigned)st * 16384;                       \
    const float* gK = kbase + (size_t)(t) * 64 * QKV_N;                       \
    const float* gV = vbase + (size_t)(t) * 64 * QKV_N;                       \
    _Pragma("unroll")                                                         \
    for (int i = 0; i < 4; i++) {                                             \
        int g = tid + i * 256; int row = g >> 4; int kg = g & 15;             \
        cpa16(ks + (unsigned)(row * 64 + ((kg ^ (row & 7)) << 2)) * 4,        \
              gK + (size_t)row * QKV_N + kg * 4);                             \
        cpa16(vs + (unsigned)(row * 64 + ((kg ^ ((row & 3) << 1)) << 2)) * 4, \
              gV + (size_t)row * QKV_N + kg * 4);                             \
    }                                                                         \
    CP_COMMIT();                                                              \
} while (0)

    A_ISSUE(0);

    for (int t = 0; t < SS / 64; t++) {
        if (t + 1 < SS / 64) { A_ISSUE(t + 1); CP_WAIT1(); }
        else CP_WAIT0();
        __syncthreads();

        const unsigned* uk = usm + (t & 1) * 4096;
        const unsigned* uv = usm + 8192 + (t & 1) * 4096;

        // S = Q K^T
        float s[8][4];
#pragma unroll
        for (int jn = 0; jn < 8; jn++)
#pragma unroll
            for (int c = 0; c < 4; c++) s[jn][c] = 0.f;

#pragma unroll
        for (int kk = 0; kk < 8; kk++) {
            int s0 = ((kk * 2) ^ grp) << 2;
            int s1 = ((kk * 2 + 1) ^ grp) << 2;
#pragma unroll
            for (int jn = 0; jn < 8; jn++) {
                int cl = jn * 8 + grp;
                unsigned bf[2];
                bf[0] = uk[cl * 64 + s0 + qd];
                bf[1] = uk[cl * 64 + s1 + qd];
                mma1688(s[jn], qa[kk], bf);
            }
        }

        // scale (+ mask only if nonzero)
        if (use_mask) {
#pragma unroll
            for (int jn = 0; jn < 8; jn++) {
                int col = t * 64 + jn * 8 + 2 * qd;
                float2 mk0 = *(const float2*)&mrowA[col];
                float2 mk1 = *(const float2*)&mrowB[col];
                s[jn][0] = fmaf(s[jn][0], scale, mk0.x);
                s[jn][1] = fmaf(s[jn][1], scale, mk0.y);
                s[jn][2] = fmaf(s[jn][2], scale, mk1.x);
                s[jn][3] = fmaf(s[jn][3], scale, mk1.y);
            }
        } else {
#pragma unroll
            for (int jn = 0; jn < 8; jn++)
#pragma unroll
                for (int c = 0; c < 4; c++) s[jn][c] *= scale;
        }

        // online softmax (quad-local stats)
        float pA = -1e30f, pB = -1e30f;
#pragma unroll
        for (int jn = 0; jn < 8; jn++) {
            pA = fmaxf(pA, fmaxf(s[jn][0], s[jn][1]));
            pB = fmaxf(pB, fmaxf(s[jn][2], s[jn][3]));
        }
        pA = fmaxf(pA, __shfl_xor_sync(0xffffffffu, pA, 1));
        pA = fmaxf(pA, __shfl_xor_sync(0xffffffffu, pA, 2));
        pB = fmaxf(pB, __shfl_xor_sync(0xffffffffu, pB, 1));
        pB = fmaxf(pB, __shfl_xor_sync(0xffffffffu, pB, 2));

        float nA = fmaxf(mA, pA), nB = fmaxf(mB, pB);
        float cA = __expf(mA - nA), cB = __expf(mB - nB);
        mA = nA; mB = nB;

        float sA = 0.f, sB = 0.f;
#pragma unroll
        for (int jn = 0; jn < 8; jn++) {
            s[jn][0] = __expf(s[jn][0] - nA);
            s[jn][1] = __expf(s[jn][1] - nA);
            s[jn][2] = __expf(s[jn][2] - nB);
            s[jn][3] = __expf(s[jn][3] - nB);
            sA += s[jn][0] + s[jn][1];
            sB += s[jn][2] + s[jn][3];
        }
        sA += __shfl_xor_sync(0xffffffffu, sA, 1);
        sA += __shfl_xor_sync(0xffffffffu, sA, 2);
        sB += __shfl_xor_sync(0xffffffffu, sB, 1);
        sB += __shfl_xor_sync(0xffffffffu, sB, 2);
        lA = lA * cA + sA;
        lB = lB * cB + sB;
#pragma unroll
        for (int jn = 0; jn < 8; jn++) {
            o[jn][0] *= cA; o[jn][1] *= cA;
            o[jn][2] *= cB; o[jn][3] *= cB;
        }

        // stage P (tf32), swizzled, per-warp rows only
#pragma unroll
        for (int jn = 0; jn < 8; jn++) {
            int kg   = jn * 2 + (qd >> 1);
            int colw = ((kg ^ grp) << 2) + 2 * (qd & 1);
            uint2 wA = { f2tf(s[jn][0]), f2tf(s[jn][1]) };
            uint2 wB = { f2tf(s[jn][2]), f2tf(s[jn][3]) };
            *(uint2*)(upw + rA * 64 + colw) = wA;
            *(uint2*)(upw + rB * 64 + colw) = wB;
        }
        __syncwarp();

        // O += P V
#pragma unroll
        for (int kk = 0; kk < 8; kk++) {
            int s0 = ((kk * 2) ^ grp) << 2;
            int s1 = ((kk * 2 + 1) ^ grp) << 2;
            unsigned pa[4];
            pa[0] = upw[rA * 64 + s0 + qd];
            pa[1] = upw[rB * 64 + s0 + qd];
            pa[2] = upw[rA * 64 + s1 + qd];
            pa[3] = upw[rB * 64 + s1 + qd];
            int rowv0 = (kk * 8 + qd) * 64;
            int rowv1 = (kk * 8 + qd + 4) * 64;
            int sw = qd << 1;
#pragma unroll
            for (int jn = 0; jn < 8; jn++) {
                int d  = jn * 8 + grp;
                int col = (((d >> 2) ^ sw) << 2) + (d & 3);
                unsigned bf[2];
                bf[0] = uv[rowv0 + col];
                bf[1] = uv[rowv1 + col];
                mma1688(o[jn], pa, bf);
            }
        }
        __syncthreads();
    }
#undef A_ISSUE

    // normalize + write values (fp32, natural) and rounded k-interleaved copy
    float iA = 1.f / lA, iB = 1.f / lB;
    size_t gRA = (size_t)b * SS + q0 + rA;
    size_t gRB = (size_t)b * SS + q0 + rB;
    // perm8 positions for logical cols (2qd, 2qd+1) within their 8-group
    const int P0 = ((2 * qd) & 3) * 2 + (qd >> 1);
    const int P1 = ((2 * qd + 1) & 3) * 2 + (qd >> 1);
#pragma unroll
    for (int jn = 0; jn < 8; jn++) {
        int col  = h * HD + jn * 8 + 2 * qd;       // natural
        int colg = h * HD + jn * 8;                // 8-group base
        float2 oA = { o[jn][0] * iA, o[jn][1] * iA };
        float2 oB = { o[jn][2] * iB, o[jn][3] * iB };
        *(float2*)&vout[gRA * D_MODEL + col] = oA;
        *(float2*)&vout[gRB * D_MODEL + col] = oB;
        vr[gRA * D_MODEL + colg + P0] = __uint_as_float(f2tf(oA.x));
        vr[gRA * D_MODEL + colg + P1] = __uint_as_float(f2tf(oA.y));
        vr[gRB * D_MODEL + colg + P0] = __uint_as_float(f2tf(oB.x));
        vr[gRB * D_MODEL + colg + P1] = __uint_as_float(f2tf(oB.y));
    }
}

// ---------------------------------------------------------------------------
// Launch
// ---------------------------------------------------------------------------
extern "C" void kernel_launch(void* const* d_in, const int* in_sizes, int n_in,
                              void* d_out, int out_size)
{
    const float* x     = (const float*)d_in[0];
    const float* mask  = (const float*)d_in[1];
    const float* W_qkv = (const float*)d_in[2];
    const float* b_qkv = (const float*)d_in[3];
    const float* W_o   = (const float*)d_in[4];
    const float* b_o   = (const float*)d_in[5];
    float* out = (float*)d_out;

    float *gx, *gwqkv, *gwo, *qkv_buf, *gvr, *vals_fb;
    int* flag;
    cudaGetSymbolAddress((void**)&gx, g_x);
    cudaGetSymbolAddress((void**)&gwqkv, g_wqkv);
    cudaGetSymbolAddress((void**)&gwo, g_wo);
    cudaGetSymbolAddress((void**)&qkv_buf, g_qkv);
    cudaGetSymbolAddress((void**)&gvr, g_vr);
    cudaGetSymbolAddress((void**)&vals_fb, g_vals);
    cudaGetSymbolAddress((void**)&flag, g_mnz);

    const size_t half = (size_t)MROWS * D_MODEL;
    float* vbuf = ((size_t)out_size >= 2 * half) ? (out + half) : vals_fb;

    static bool attr_done = false;
    if (!attr_done) {
        cudaFuncSetAttribute(gemm_tf32_pipe,
                             cudaFuncAttributeMaxDynamicSharedMemorySize,
                             GEMM_SMEM_BYTES);
        cudaFuncSetAttribute(attn_pipe,
                             cudaFuncAttributeMaxDynamicSharedMemorySize,
                             ATT_SMEM_BYTES);
        attr_done = true;
    }

    // mask flag + pre-rounded (and A-interleaved) inputs
    reset_flag_kernel<<<1, 1>>>(flag);
    mask_scan_kernel<<<1024, 256>>>((const float4*)mask, SS * SS / 4, flag);
    round_perm_kernel<<<2048, 256>>>((const float4*)x, gx, MROWS * D_IN / 4);
    round_tf32_kernel<<<1024, 256>>>((const float4*)W_qkv, (float4*)gwqkv,
                                     D_IN * QKV_N / 4);
    round_tf32_kernel<<<512, 256>>>((const float4*)W_o, (float4*)gwo,
                                    D_MODEL * D_MODEL / 4);

    // 1) qkv = x @ W_qkv + b_qkv  (rounded natural output)
    {
        dim3 grid(QKV_N / 128, MROWS / 128);
        gemm_tf32_pipe<<<grid, 256, GEMM_SMEM_BYTES>>>(
            gx, gwqkv, b_qkv, qkv_buf, MROWS, QKV_N, D_IN, 1);
    }

    // 2) attention -> values (fp32) + rounded interleaved copy
    {
        dim3 grid(SS / 128, BB * NH);
        attn_pipe<<<grid, 256, ATT_SMEM_BYTES>>>(qkv_buf, mask, flag, vbuf, gvr);
    }

    // 3) out = values @ W_o + b_o
    {
        dim3 grid(D_MODEL / 128, MROWS / 128);
        gemm_tf32_pipe<<<grid, 256, GEMM_SMEM_BYTES>>>(
            gvr, gwo, b_o, out, MROWS, D_MODEL, D_MODEL, 0);
    }
}